// round 4
// baseline (speedup 1.0000x reference)
#include <cuda_runtime.h>
#include <cstdint>

// Problem constants
#define DD   4096
#define OBJN 20
#define MCNT 1000
#define FR   20
#define BB   4
#define QQ   4
#define NROWS 32      // compacted rows: 16 high + 16 low
#define KSPLIT 32

#define RP_ELEMS 26214400ull          // Q*B*F*OBJ*D
#define OUT_HIGH (2ull*RP_ELEMS)      // 52428800
#define OUT_LOW  (2ull*RP_ELEMS + 16ull)

typedef unsigned long long ull;

// ---------------- scratch (device globals; no allocation allowed) ----------
__device__ int   g_high[16];
__device__ int   g_low[16];
__device__ int   g_rowbf[32];                 // compact row -> b*20+f
__device__ float g_invn[BB*FR*OBJN];          // per-region inverse norms
__device__ float g_Rmax[BB*FR*DD];            // normalized max-pooled input rows
__device__ float g_memmp[2*MCNT*DD];          // normalized max-pooled mem rows
__device__ float g_part[KSPLIT*2*NROWS*1024]; // k-split partial scores
__device__ int   g_sim[64];                   // [sel][32] argmax results

// ---------------- helpers ---------------------------------------------------
__device__ __forceinline__ float blockReduceSum256(float v, float* sh) {
    #pragma unroll
    for (int o = 16; o > 0; o >>= 1) v += __shfl_xor_sync(0xffffffffu, v, o);
    int lane = threadIdx.x & 31, w = threadIdx.x >> 5;
    if (lane == 0) sh[w] = v;
    __syncthreads();
    if (threadIdx.x < 32) {
        float r = (threadIdx.x < 8) ? sh[threadIdx.x] : 0.f;
        #pragma unroll
        for (int o = 4; o > 0; o >>= 1) r += __shfl_xor_sync(0xffffffffu, r, o);
        if (threadIdx.x == 0) sh[0] = r;
    }
    __syncthreads();
    float res = sh[0];
    __syncthreads();
    return res;
}

// packed f32x2 FMA: d += a * b (elementwise on 2 packed floats)
__device__ __forceinline__ void ffma2(ull& d, ull a, ull b) {
    asm("fma.rn.f32x2 %0, %1, %2, %0;" : "+l"(d) : "l"(a), "l"(b));
}

// ---------------- K1: top-k / rank-selected indices -------------------------
__global__ void k_idx(const float* __restrict__ qr, const int* __restrict__ rnd) {
    int t = threadIdx.x;
    if (t < 16) {
        int b = t >> 2;
        const float* v = qr + t * FR;   // [B,Q,F], t=b*Q+q
        int hi = 0; float hv = v[0];
        for (int i = 1; i < FR; i++) { float x = v[i]; if (x > hv) { hv = x; hi = i; } }
        int r = rnd[t];
        int lo = 0;
        for (int i = 0; i < FR; i++) {
            int rank = 0;
            float c = v[i];
            for (int j = 0; j < FR; j++) {
                float a = v[j];
                rank += (a < c) || (a == c && j < i);
            }
            if (rank == r) { lo = i; break; }
        }
        g_high[t] = hi;
        g_low[t]  = lo;
        g_rowbf[t]      = b * FR + hi;   // compact rows 0..15 : high
        g_rowbf[16 + t] = b * FR + lo;   // compact rows 16..31: low
    }
}

// ---------------- K2: per-region inv norms + normalized maxpool of input ----
__global__ void __launch_bounds__(256) k_rmax(const float* __restrict__ inp) {
    int bf = blockIdx.x;             // b*20+f, 80 blocks
    int t  = threadIdx.x;
    __shared__ float sh[32];
    __shared__ float s_inv[OBJN];
    const float* base = inp + (size_t)bf * (OBJN * DD);

    for (int o = 0; o < OBJN; o++) {
        const float4* p = (const float4*)(base + o * DD);
        float s = 0.f;
        #pragma unroll
        for (int i = 0; i < 4; i++) {
            float4 v = __ldg(p + t + i * 256);
            s += v.x*v.x + v.y*v.y + v.z*v.z + v.w*v.w;
        }
        float tot = blockReduceSum256(s, sh);
        if (t == 0) s_inv[o] = 1.0f / fmaxf(sqrtf(tot), 1e-12f);
    }
    __syncthreads();
    if (t < OBJN) g_invn[bf * OBJN + t] = s_inv[t];

    float4 mx[4];
    #pragma unroll
    for (int i = 0; i < 4; i++) mx[i] = make_float4(-3.4e38f, -3.4e38f, -3.4e38f, -3.4e38f);
    for (int o = 0; o < OBJN; o++) {
        float inv = s_inv[o];
        const float4* p = (const float4*)(base + o * DD);
        #pragma unroll
        for (int i = 0; i < 4; i++) {
            float4 v = __ldg(p + t + i * 256);
            mx[i].x = fmaxf(mx[i].x, v.x * inv);
            mx[i].y = fmaxf(mx[i].y, v.y * inv);
            mx[i].z = fmaxf(mx[i].z, v.z * inv);
            mx[i].w = fmaxf(mx[i].w, v.w * inv);
        }
    }
    float s = 0.f;
    #pragma unroll
    for (int i = 0; i < 4; i++) s += mx[i].x*mx[i].x + mx[i].y*mx[i].y + mx[i].z*mx[i].z + mx[i].w*mx[i].w;
    float tot = blockReduceSum256(s, sh);
    float inv2 = 1.0f / fmaxf(sqrtf(tot), 1e-12f);
    float4* op = (float4*)(g_Rmax + (size_t)bf * DD);
    #pragma unroll
    for (int i = 0; i < 4; i++) {
        float4 v = mx[i];
        v.x *= inv2; v.y *= inv2; v.z *= inv2; v.w *= inv2;
        op[t + i * 256] = v;
    }
}

// ---------------- K3: mem maxpool + normalize (dominant, 655 MB stream) -----
__global__ void __launch_bounds__(256) k_memmp(const float* __restrict__ mem1,
                                               const float* __restrict__ mem2) {
    int m = blockIdx.x, sel = blockIdx.y;
    const float* mem = sel ? mem2 : mem1;
    int t = threadIdx.x;
    __shared__ float sh[32];
    const float4* base = (const float4*)(mem + (size_t)m * (OBJN * DD));
    // two independent accumulator sets (even/odd obj) -> 8 loads in flight
    float4 ma[4], mb[4];
    #pragma unroll
    for (int i = 0; i < 4; i++) {
        ma[i] = make_float4(-3.4e38f, -3.4e38f, -3.4e38f, -3.4e38f);
        mb[i] = ma[i];
    }
    #pragma unroll 2
    for (int o = 0; o < OBJN; o += 2) {
        const float4* p0 = base + (o + 0) * (DD / 4);
        const float4* p1 = base + (o + 1) * (DD / 4);
        float4 v0[4], v1[4];
        #pragma unroll
        for (int i = 0; i < 4; i++) v0[i] = __ldcs(p0 + t + i * 256);
        #pragma unroll
        for (int i = 0; i < 4; i++) v1[i] = __ldcs(p1 + t + i * 256);
        #pragma unroll
        for (int i = 0; i < 4; i++) {
            ma[i].x = fmaxf(ma[i].x, v0[i].x);
            ma[i].y = fmaxf(ma[i].y, v0[i].y);
            ma[i].z = fmaxf(ma[i].z, v0[i].z);
            ma[i].w = fmaxf(ma[i].w, v0[i].w);
            mb[i].x = fmaxf(mb[i].x, v1[i].x);
            mb[i].y = fmaxf(mb[i].y, v1[i].y);
            mb[i].z = fmaxf(mb[i].z, v1[i].z);
            mb[i].w = fmaxf(mb[i].w, v1[i].w);
        }
    }
    float s = 0.f;
    #pragma unroll
    for (int i = 0; i < 4; i++) {
        ma[i].x = fmaxf(ma[i].x, mb[i].x);
        ma[i].y = fmaxf(ma[i].y, mb[i].y);
        ma[i].z = fmaxf(ma[i].z, mb[i].z);
        ma[i].w = fmaxf(ma[i].w, mb[i].w);
        s += ma[i].x*ma[i].x + ma[i].y*ma[i].y + ma[i].z*ma[i].z + ma[i].w*ma[i].w;
    }
    float tot = blockReduceSum256(s, sh);
    float inv = 1.0f / fmaxf(sqrtf(tot), 1e-12f);
    float4* op = (float4*)(g_memmp + ((size_t)sel * MCNT + m) * DD);
    #pragma unroll
    for (int i = 0; i < 4; i++) {
        float4 v = ma[i];
        v.x *= inv; v.y *= inv; v.z *= inv; v.w *= inv;
        op[t + i * 256] = v;
    }
}

// ---------------- K4: fp32 score GEMM (32 x 1000 x 4096), f32x2, k-split ----
__global__ void __launch_bounds__(256) k_scores() {
    int sel = blockIdx.z;
    int m0  = blockIdx.x * 128;             // 8 m-tiles of 128
    int kb  = blockIdx.y * (DD / KSPLIT);   // 128-wide K segment
    int t   = threadIdx.x;
    __shared__ float Rs[NROWS][64];         // [row][k]  (row stride 64: f4-aligned)
    __shared__ float Ms[128][66];           // [col][k]  (pad 66: 8B-aligned, 2-way)
    __shared__ int   rowbase[NROWS];
    if (t < NROWS) rowbase[t] = g_rowbf[t] * DD;

    ull acc[4][4];
    #pragma unroll
    for (int i = 0; i < 4; i++)
        #pragma unroll
        for (int j = 0; j < 4; j++) acc[i][j] = 0ull;

    const float* memmp = g_memmp + (size_t)sel * MCNT * DD;
    int c  = t & 31;     // base col
    int rt = t >> 5;     // row group 0..7 -> rows rt*4 .. rt*4+3

    for (int kc = 0; kc < DD / KSPLIT; kc += 64) {   // 2 chunks of 64
        __syncthreads();
        int k0 = kb + kc;
        // Rs: 32 rows x 64 k  (2048 floats, 8/thread, coalesced along k)
        for (int i = t; i < NROWS * 64; i += 256) {
            int r = i >> 6, k = i & 63;
            Rs[r][k] = g_Rmax[rowbase[r] + k0 + k];
        }
        // Ms: 128 cols x 64 k via float4 global loads (coalesced)
        for (int i = t; i < 128 * 16; i += 256) {
            int cc = i >> 4, kq = (i & 15) << 2;     // kq = 0,4,...,60
            int m = m0 + cc;
            float4 v = (m < MCNT)
                ? __ldg((const float4*)(memmp + (size_t)m * DD + k0 + kq))
                : make_float4(0.f, 0.f, 0.f, 0.f);
            ull* w = (ull*)&Ms[cc][kq];              // 8B-aligned (66*cc even, kq even)
            ull w0, w1;
            asm("mov.b64 %0, {%1,%2};" : "=l"(w0) : "f"(v.x), "f"(v.y));
            asm("mov.b64 %0, {%1,%2};" : "=l"(w1) : "f"(v.z), "f"(v.w));
            w[0] = w0; w[1] = w1;
        }
        __syncthreads();
        #pragma unroll 8
        for (int k = 0; k < 64; k += 2) {
            ull rv[4], mv[4];
            #pragma unroll
            for (int i = 0; i < 4; i++) rv[i] = *(const ull*)&Rs[rt * 4 + i][k];
            #pragma unroll
            for (int j = 0; j < 4; j++) mv[j] = *(const ull*)&Ms[c + j * 32][k];
            #pragma unroll
            for (int i = 0; i < 4; i++)
                #pragma unroll
                for (int j = 0; j < 4; j++) ffma2(acc[i][j], rv[i], mv[j]);
        }
    }
    // lane reduce (deterministic: lo + hi) and partial store
    float* part = g_part + (((size_t)blockIdx.y * 2 + sel) * NROWS) * 1024;
    #pragma unroll
    for (int i = 0; i < 4; i++)
        #pragma unroll
        for (int j = 0; j < 4; j++) {
            unsigned lo, hi;
            asm("mov.b64 {%0,%1}, %2;" : "=r"(lo), "=r"(hi) : "l"(acc[i][j]));
            float s = __uint_as_float(lo) + __uint_as_float(hi);
            int row = rt * 4 + i;
            int m   = m0 + c + j * 32;
            part[row * 1024 + m] = s;
        }
}

// ---------------- K4b: deterministic reduce + argmax (+ sim outputs) --------
__global__ void __launch_bounds__(256) k_argmax(float* __restrict__ out) {
    int row = blockIdx.x;            // 0..63
    int sel = row >> 5, r = row & 31;
    int t = threadIdx.x;
    __shared__ unsigned long long sh[8];
    unsigned long long best = 0ull;
    for (int m = t; m < MCNT; m += 256) {
        float s = 0.f;
        #pragma unroll
        for (int ks = 0; ks < KSPLIT; ks++)
            s += g_part[(((size_t)ks * 2 + sel) * NROWS + r) * 1024 + m];
        unsigned u = __float_as_uint(s);
        u ^= (u >> 31) ? 0xFFFFFFFFu : 0x80000000u;
        unsigned long long pv = ((unsigned long long)u << 32) | (unsigned)(0xFFFFFFFFu - (unsigned)m);
        best = (pv > best) ? pv : best;
    }
    #pragma unroll
    for (int o = 16; o > 0; o >>= 1) {
        unsigned long long x = __shfl_xor_sync(0xffffffffu, best, o);
        best = (x > best) ? x : best;
    }
    if ((t & 31) == 0) sh[t >> 5] = best;
    __syncthreads();
    if (t == 0) {
        #pragma unroll
        for (int w = 1; w < 8; w++) best = (sh[w] > best) ? sh[w] : best;
        int sim = (int)(0xFFFFFFFFu - (unsigned)(best & 0xFFFFFFFFu));
        g_sim[sel * 32 + r] = sim;
        // fused sim outputs: out index = q*4+b for g_sim bq = b*4+q
        if (sel == 1 && r < 16) {
            int b = r >> 2, q = r & 3;
            out[OUT_HIGH + q * 4 + b] = (float)sim;   // sim2 at high row
        }
        if (sel == 0 && r >= 16) {
            int bq = r - 16;
            int b = bq >> 2, q = bq & 3;
            out[OUT_LOW + q * 4 + b] = (float)sim;    // sim1 at low row
        }
    }
}

// ---------------- K5: assemble Rp / Rn (210 MB writes) ----------------------
__global__ void __launch_bounds__(256) k_out(const float* __restrict__ inp,
                                             const float* __restrict__ mem1,
                                             const float* __restrict__ mem2,
                                             float* __restrict__ out) {
    int id = blockIdx.x;             // 0..319 == q*80 + b*20 + f
    int o  = blockIdx.y;             // 0..19
    int q  = id / 80;
    int rem = id - q * 80;
    int b  = rem / FR;
    int f  = rem - b * FR;
    int bq = b * QQ + q;
    int hi = g_high[bq], lo = g_low[bq];
    int t  = threadIdx.x;

    size_t outoff = ((size_t)id * OBJN + o) * DD;
    float4* op = (float4*)(out + outoff);                 // Rp
    float4* on = (float4*)(out + RP_ELEMS + outoff);      // Rn
    const float4* pr = (const float4*)(inp + (((size_t)(b * FR + f)) * OBJN + o) * DD);
    float invn = g_invn[(b * FR + f) * OBJN + o];

    if (f != hi && f != lo) {
        #pragma unroll
        for (int i = 0; i < 4; i++) {
            float4 v = __ldg(pr + t + i * 256);
            v.x *= invn; v.y *= invn; v.z *= invn; v.w *= invn;
            __stcs(op + t + i * 256, v);
            __stcs(on + t + i * 256, v);
        }
    } else if (f == hi) {
        // Rn <- mem2[sim2 @ low]; Rp <- R
        int s = g_sim[32 + 16 + bq];
        const float4* pm = (const float4*)(mem2 + (size_t)s * (OBJN * DD) + o * DD);
        #pragma unroll
        for (int i = 0; i < 4; i++) {
            float4 v = __ldg(pr + t + i * 256);
            v.x *= invn; v.y *= invn; v.z *= invn; v.w *= invn;
            __stcs(op + t + i * 256, v);
            float4 w = __ldg(pm + t + i * 256);
            __stcs(on + t + i * 256, w);
        }
    } else {
        // f == lo: Rp <- mem1[sim1 @ low]; Rn <- R
        int s = g_sim[16 + bq];
        const float4* pm = (const float4*)(mem1 + (size_t)s * (OBJN * DD) + o * DD);
        #pragma unroll
        for (int i = 0; i < 4; i++) {
            float4 w = __ldg(pm + t + i * 256);
            __stcs(op + t + i * 256, w);
            float4 v = __ldg(pr + t + i * 256);
            v.x *= invn; v.y *= invn; v.z *= invn; v.w *= invn;
            __stcs(on + t + i * 256, v);
        }
    }
}

// ---------------- launch -----------------------------------------------------
extern "C" void kernel_launch(void* const* d_in, const int* in_sizes, int n_in,
                              void* d_out, int out_size) {
    const float* qr   = (const float*)d_in[0];   // [4,4,20]
    const float* inp  = (const float*)d_in[1];   // [4,20,20,4096]
    const float* mem1 = (const float*)d_in[2];   // [1000,81920]
    const float* mem2 = (const float*)d_in[3];   // [1000,81920]
    const int*   rnd  = (const int*)d_in[4];     // [4,4,1]
    float* out = (float*)d_out;

    k_idx<<<1, 32>>>(qr, rnd);
    k_rmax<<<80, 256>>>(inp);
    k_memmp<<<dim3(MCNT, 2), 256>>>(mem1, mem2);
    k_scores<<<dim3(8, KSPLIT, 2), 256>>>();
    k_argmax<<<64, 256>>>(out);
    k_out<<<dim3(320, OBJN), 256>>>(inp, mem1, mem2, out);
}

// round 5
// speedup vs baseline: 1.0498x; 1.0498x over previous
#include <cuda_runtime.h>
#include <cstdint>

// Problem constants
#define DD   4096
#define OBJN 20
#define MCNT 1000
#define FR   20
#define BB   4
#define QQ   4
#define NROWS 32      // compacted rows: 16 high + 16 low
#define KSPLIT 16

#define RP_ELEMS 26214400ull          // Q*B*F*OBJ*D
#define OUT_HIGH (2ull*RP_ELEMS)      // 52428800
#define OUT_LOW  (2ull*RP_ELEMS + 16ull)

typedef unsigned long long ull;

// ---------------- scratch (device globals; no allocation allowed) ----------
__device__ int   g_high[16];
__device__ int   g_low[16];
__device__ int   g_rowbf[32];                 // compact row -> b*20+f
__device__ float g_invn[BB*FR*OBJN];          // per-region inverse norms
__device__ float g_Rmax[BB*FR*DD];            // normalized max-pooled input rows
__device__ float g_memmp[2*MCNT*DD];          // normalized max-pooled mem rows
__device__ float g_part[KSPLIT*2*NROWS*1024]; // k-split partial scores
__device__ int   g_sim[64];                   // [sel][32] argmax results

// ---------------- helpers ---------------------------------------------------
__device__ __forceinline__ float blockReduceSum256(float v, float* sh) {
    #pragma unroll
    for (int o = 16; o > 0; o >>= 1) v += __shfl_xor_sync(0xffffffffu, v, o);
    int lane = threadIdx.x & 31, w = threadIdx.x >> 5;
    if (lane == 0) sh[w] = v;
    __syncthreads();
    if (threadIdx.x < 32) {
        float r = (threadIdx.x < 8) ? sh[threadIdx.x] : 0.f;
        #pragma unroll
        for (int o = 4; o > 0; o >>= 1) r += __shfl_xor_sync(0xffffffffu, r, o);
        if (threadIdx.x == 0) sh[0] = r;
    }
    __syncthreads();
    float res = sh[0];
    __syncthreads();
    return res;
}

// packed f32x2 FMA: d += a * b (elementwise on 2 packed floats)
__device__ __forceinline__ void ffma2(ull& d, ull a, ull b) {
    asm("fma.rn.f32x2 %0, %1, %2, %0;" : "+l"(d) : "l"(a), "l"(b));
}

// ---------------- K1: top-k / rank-selected indices -------------------------
__global__ void k_idx(const float* __restrict__ qr, const int* __restrict__ rnd) {
    int t = threadIdx.x;
    if (t < 16) {
        int b = t >> 2;
        const float* v = qr + t * FR;   // [B,Q,F], t=b*Q+q
        int hi = 0; float hv = v[0];
        for (int i = 1; i < FR; i++) { float x = v[i]; if (x > hv) { hv = x; hi = i; } }
        int r = rnd[t];
        int lo = 0;
        for (int i = 0; i < FR; i++) {
            int rank = 0;
            float c = v[i];
            for (int j = 0; j < FR; j++) {
                float a = v[j];
                rank += (a < c) || (a == c && j < i);
            }
            if (rank == r) { lo = i; break; }
        }
        g_high[t] = hi;
        g_low[t]  = lo;
        g_rowbf[t]      = b * FR + hi;   // compact rows 0..15 : high
        g_rowbf[16 + t] = b * FR + lo;   // compact rows 16..31: low
    }
}

// ---------------- K2: per-region inv norms + normalized maxpool of input ----
__global__ void __launch_bounds__(256) k_rmax(const float* __restrict__ inp) {
    int bf = blockIdx.x;             // b*20+f, 80 blocks
    int t  = threadIdx.x;
    __shared__ float sh[32];
    __shared__ float s_inv[OBJN];
    const float* base = inp + (size_t)bf * (OBJN * DD);

    for (int o = 0; o < OBJN; o++) {
        const float4* p = (const float4*)(base + o * DD);
        float s = 0.f;
        #pragma unroll
        for (int i = 0; i < 4; i++) {
            float4 v = __ldg(p + t + i * 256);
            s += v.x*v.x + v.y*v.y + v.z*v.z + v.w*v.w;
        }
        float tot = blockReduceSum256(s, sh);
        if (t == 0) s_inv[o] = 1.0f / fmaxf(sqrtf(tot), 1e-12f);
    }
    __syncthreads();
    if (t < OBJN) g_invn[bf * OBJN + t] = s_inv[t];

    float4 mx[4];
    #pragma unroll
    for (int i = 0; i < 4; i++) mx[i] = make_float4(-3.4e38f, -3.4e38f, -3.4e38f, -3.4e38f);
    for (int o = 0; o < OBJN; o++) {
        float inv = s_inv[o];
        const float4* p = (const float4*)(base + o * DD);
        #pragma unroll
        for (int i = 0; i < 4; i++) {
            float4 v = __ldg(p + t + i * 256);
            mx[i].x = fmaxf(mx[i].x, v.x * inv);
            mx[i].y = fmaxf(mx[i].y, v.y * inv);
            mx[i].z = fmaxf(mx[i].z, v.z * inv);
            mx[i].w = fmaxf(mx[i].w, v.w * inv);
        }
    }
    float s = 0.f;
    #pragma unroll
    for (int i = 0; i < 4; i++) s += mx[i].x*mx[i].x + mx[i].y*mx[i].y + mx[i].z*mx[i].z + mx[i].w*mx[i].w;
    float tot = blockReduceSum256(s, sh);
    float inv2 = 1.0f / fmaxf(sqrtf(tot), 1e-12f);
    float4* op = (float4*)(g_Rmax + (size_t)bf * DD);
    #pragma unroll
    for (int i = 0; i < 4; i++) {
        float4 v = mx[i];
        v.x *= inv2; v.y *= inv2; v.z *= inv2; v.w *= inv2;
        op[t + i * 256] = v;
    }
}

// ---------------- K3: mem maxpool + normalize (dominant, 655 MB stream) -----
__global__ void __launch_bounds__(256) k_memmp(const float* __restrict__ mem1,
                                               const float* __restrict__ mem2) {
    int m = blockIdx.x, sel = blockIdx.y;
    const float* mem = sel ? mem2 : mem1;
    int t = threadIdx.x;
    __shared__ float sh[32];
    const float4* base = (const float4*)(mem + (size_t)m * (OBJN * DD));
    float4 mx[4];
    #pragma unroll
    for (int i = 0; i < 4; i++) mx[i] = make_float4(-3.4e38f, -3.4e38f, -3.4e38f, -3.4e38f);
    for (int o = 0; o < OBJN; o++) {
        const float4* p = base + o * (DD / 4);
        #pragma unroll
        for (int i = 0; i < 4; i++) {
            float4 v = __ldcs(p + t + i * 256);   // streaming: don't pollute L2
            mx[i].x = fmaxf(mx[i].x, v.x);
            mx[i].y = fmaxf(mx[i].y, v.y);
            mx[i].z = fmaxf(mx[i].z, v.z);
            mx[i].w = fmaxf(mx[i].w, v.w);
        }
    }
    float s = 0.f;
    #pragma unroll
    for (int i = 0; i < 4; i++) s += mx[i].x*mx[i].x + mx[i].y*mx[i].y + mx[i].z*mx[i].z + mx[i].w*mx[i].w;
    float tot = blockReduceSum256(s, sh);
    float inv = 1.0f / fmaxf(sqrtf(tot), 1e-12f);
    float4* op = (float4*)(g_memmp + ((size_t)sel * MCNT + m) * DD);
    #pragma unroll
    for (int i = 0; i < 4; i++) {
        float4 v = mx[i];
        v.x *= inv; v.y *= inv; v.z *= inv; v.w *= inv;
        op[t + i * 256] = v;
    }
}

// ---------------- K4: fp32 score GEMM (32 x 1000 x 4096), f32x2, k-split ----
// 64-col m-tiles: grid (16, KSPLIT, 2) = 512 blocks, smem 25KB, occ 4+ CTA/SM
__global__ void __launch_bounds__(256) k_scores() {
    int sel = blockIdx.z;
    int m0  = blockIdx.x * 64;              // 16 m-tiles of 64
    int kb  = blockIdx.y * (DD / KSPLIT);   // 256-wide K segment
    int t   = threadIdx.x;
    __shared__ float Rs[NROWS][64];         // [row][k]
    __shared__ float Ms[64][66];            // [col][k]  (pad 66: 8B-aligned)
    __shared__ int   rowbase[NROWS];
    if (t < NROWS) rowbase[t] = g_rowbf[t] * DD;

    ull acc[4][2];
    #pragma unroll
    for (int i = 0; i < 4; i++) { acc[i][0] = 0ull; acc[i][1] = 0ull; }

    const float* memmp = g_memmp + (size_t)sel * MCNT * DD;
    int c  = t & 31;     // base col
    int rt = t >> 5;     // row group 0..7 -> rows rt*4 .. rt*4+3

    for (int kc = 0; kc < DD / KSPLIT; kc += 64) {   // 4 chunks of 64
        __syncthreads();
        int k0 = kb + kc;
        // Rs: 32 rows x 64 k  (2048 floats, 8/thread, coalesced along k)
        for (int i = t; i < NROWS * 64; i += 256) {
            int r = i >> 6, k = i & 63;
            Rs[r][k] = g_Rmax[rowbase[r] + k0 + k];
        }
        // Ms: 64 cols x 64 k via float4 global loads (coalesced)
        for (int i = t; i < 64 * 16; i += 256) {
            int cc = i >> 4, kq = (i & 15) << 2;     // kq = 0,4,...,60
            int m = m0 + cc;
            float4 v = (m < MCNT)
                ? __ldg((const float4*)(memmp + (size_t)m * DD + k0 + kq))
                : make_float4(0.f, 0.f, 0.f, 0.f);
            ull* w = (ull*)&Ms[cc][kq];              // 8B-aligned (66*cc even, kq even)
            ull w0, w1;
            asm("mov.b64 %0, {%1,%2};" : "=l"(w0) : "f"(v.x), "f"(v.y));
            asm("mov.b64 %0, {%1,%2};" : "=l"(w1) : "f"(v.z), "f"(v.w));
            w[0] = w0; w[1] = w1;
        }
        __syncthreads();
        #pragma unroll 8
        for (int k = 0; k < 64; k += 2) {
            ull rv[4], mv[2];
            #pragma unroll
            for (int i = 0; i < 4; i++) rv[i] = *(const ull*)&Rs[rt * 4 + i][k];
            mv[0] = *(const ull*)&Ms[c][k];
            mv[1] = *(const ull*)&Ms[c + 32][k];
            #pragma unroll
            for (int i = 0; i < 4; i++) {
                ffma2(acc[i][0], rv[i], mv[0]);
                ffma2(acc[i][1], rv[i], mv[1]);
            }
        }
    }
    // lane reduce (deterministic: lo + hi) and partial store
    float* part = g_part + (((size_t)blockIdx.y * 2 + sel) * NROWS) * 1024;
    #pragma unroll
    for (int i = 0; i < 4; i++)
        #pragma unroll
        for (int j = 0; j < 2; j++) {
            unsigned lo, hi;
            asm("mov.b64 {%0,%1}, %2;" : "=r"(lo), "=r"(hi) : "l"(acc[i][j]));
            float s = __uint_as_float(lo) + __uint_as_float(hi);
            int row = rt * 4 + i;
            int m   = m0 + c + j * 32;
            part[row * 1024 + m] = s;
        }
}

// ---------------- K4b: deterministic reduce + argmax (+ sim outputs) --------
__global__ void __launch_bounds__(256) k_argmax(float* __restrict__ out) {
    int row = blockIdx.x;            // 0..63
    int sel = row >> 5, r = row & 31;
    int t = threadIdx.x;
    __shared__ unsigned long long sh[8];
    unsigned long long best = 0ull;
    for (int m = t; m < MCNT; m += 256) {
        float s = 0.f;
        #pragma unroll
        for (int ks = 0; ks < KSPLIT; ks++)
            s += g_part[(((size_t)ks * 2 + sel) * NROWS + r) * 1024 + m];
        unsigned u = __float_as_uint(s);
        u ^= (u >> 31) ? 0xFFFFFFFFu : 0x80000000u;
        unsigned long long pv = ((unsigned long long)u << 32) | (unsigned)(0xFFFFFFFFu - (unsigned)m);
        best = (pv > best) ? pv : best;
    }
    #pragma unroll
    for (int o = 16; o > 0; o >>= 1) {
        unsigned long long x = __shfl_xor_sync(0xffffffffu, best, o);
        best = (x > best) ? x : best;
    }
    if ((t & 31) == 0) sh[t >> 5] = best;
    __syncthreads();
    if (t == 0) {
        #pragma unroll
        for (int w = 1; w < 8; w++) best = (sh[w] > best) ? sh[w] : best;
        int sim = (int)(0xFFFFFFFFu - (unsigned)(best & 0xFFFFFFFFu));
        g_sim[sel * 32 + r] = sim;
        // fused sim outputs: out index = q*4+b for g_sim bq = b*4+q
        if (sel == 1 && r < 16) {
            int b = r >> 2, q = r & 3;
            out[OUT_HIGH + q * 4 + b] = (float)sim;   // sim2 at high row
        }
        if (sel == 0 && r >= 16) {
            int bq = r - 16;
            int b = bq >> 2, q = bq & 3;
            out[OUT_LOW + q * 4 + b] = (float)sim;    // sim1 at low row
        }
    }
}

// ---------------- K5: assemble Rp / Rn (210 MB writes) ----------------------
__global__ void __launch_bounds__(256) k_out(const float* __restrict__ inp,
                                             const float* __restrict__ mem1,
                                             const float* __restrict__ mem2,
                                             float* __restrict__ out) {
    int id = blockIdx.x;             // 0..319 == q*80 + b*20 + f
    int o  = blockIdx.y;             // 0..19
    int q  = id / 80;
    int rem = id - q * 80;
    int b  = rem / FR;
    int f  = rem - b * FR;
    int bq = b * QQ + q;
    int hi = g_high[bq], lo = g_low[bq];
    int t  = threadIdx.x;

    size_t outoff = ((size_t)id * OBJN + o) * DD;
    float4* op = (float4*)(out + outoff);                 // Rp
    float4* on = (float4*)(out + RP_ELEMS + outoff);      // Rn
    const float4* pr = (const float4*)(inp + (((size_t)(b * FR + f)) * OBJN + o) * DD);
    float invn = g_invn[(b * FR + f) * OBJN + o];

    if (f != hi && f != lo) {
        #pragma unroll
        for (int i = 0; i < 4; i++) {
            float4 v = __ldg(pr + t + i * 256);
            v.x *= invn; v.y *= invn; v.z *= invn; v.w *= invn;
            __stcs(op + t + i * 256, v);
            __stcs(on + t + i * 256, v);
        }
    } else if (f == hi) {
        // Rn <- mem2[sim2 @ low]; Rp <- R
        int s = g_sim[32 + 16 + bq];
        const float4* pm = (const float4*)(mem2 + (size_t)s * (OBJN * DD) + o * DD);
        #pragma unroll
        for (int i = 0; i < 4; i++) {
            float4 v = __ldg(pr + t + i * 256);
            v.x *= invn; v.y *= invn; v.z *= invn; v.w *= invn;
            __stcs(op + t + i * 256, v);
            float4 w = __ldg(pm + t + i * 256);
            __stcs(on + t + i * 256, w);
        }
    } else {
        // f == lo: Rp <- mem1[sim1 @ low]; Rn <- R
        int s = g_sim[16 + bq];
        const float4* pm = (const float4*)(mem1 + (size_t)s * (OBJN * DD) + o * DD);
        #pragma unroll
        for (int i = 0; i < 4; i++) {
            float4 w = __ldg(pm + t + i * 256);
            __stcs(op + t + i * 256, w);
            float4 v = __ldg(pr + t + i * 256);
            v.x *= invn; v.y *= invn; v.z *= invn; v.w *= invn;
            __stcs(on + t + i * 256, v);
        }
    }
}

// ---------------- launch -----------------------------------------------------
extern "C" void kernel_launch(void* const* d_in, const int* in_sizes, int n_in,
                              void* d_out, int out_size) {
    const float* qr   = (const float*)d_in[0];   // [4,4,20]
    const float* inp  = (const float*)d_in[1];   // [4,20,20,4096]
    const float* mem1 = (const float*)d_in[2];   // [1000,81920]
    const float* mem2 = (const float*)d_in[3];   // [1000,81920]
    const int*   rnd  = (const int*)d_in[4];     // [4,4,1]
    float* out = (float*)d_out;

    k_idx<<<1, 32>>>(qr, rnd);
    k_rmax<<<80, 256>>>(inp);
    k_memmp<<<dim3(MCNT, 2), 256>>>(mem1, mem2);
    k_scores<<<dim3(16, KSPLIT, 2), 256>>>();
    k_argmax<<<64, 256>>>(out);
    k_out<<<dim3(320, OBJN), 256>>>(inp, mem1, mem2, out);
}

// round 6
// speedup vs baseline: 1.2173x; 1.1595x over previous
#include <cuda_runtime.h>
#include <cstdint>

// Problem constants
#define DD   4096
#define OBJN 20
#define MCNT 1000
#define FR   20
#define BB   4
#define QQ   4
#define NROWS 32      // compacted rows: 16 high + 16 low
#define KSPLIT 16

#define RP_ELEMS 26214400ull          // Q*B*F*OBJ*D
#define OUT_HIGH (2ull*RP_ELEMS)      // 52428800
#define OUT_LOW  (2ull*RP_ELEMS + 16ull)

typedef unsigned long long ull;

// ---------------- scratch (device globals; no allocation allowed) ----------
__device__ int   g_high[16];
__device__ int   g_low[16];
__device__ int   g_rowbf[32];                 // compact row -> b*20+f
__device__ float g_invn[BB*FR*OBJN];          // per-region inverse norms
__device__ float g_Rmax[BB*FR*DD];            // normalized max-pooled input rows
__device__ float g_memmp[2*MCNT*DD];          // normalized max-pooled mem rows
__device__ float g_part[KSPLIT*2*NROWS*1024]; // k-split partial scores
__device__ int   g_sim[64];                   // [sel][32] argmax results

// ---------------- helpers ---------------------------------------------------
__device__ __forceinline__ float blockReduceSum256(float v, float* sh) {
    #pragma unroll
    for (int o = 16; o > 0; o >>= 1) v += __shfl_xor_sync(0xffffffffu, v, o);
    int lane = threadIdx.x & 31, w = threadIdx.x >> 5;
    if (lane == 0) sh[w] = v;
    __syncthreads();
    if (threadIdx.x < 32) {
        float r = (threadIdx.x < 8) ? sh[threadIdx.x] : 0.f;
        #pragma unroll
        for (int o = 4; o > 0; o >>= 1) r += __shfl_xor_sync(0xffffffffu, r, o);
        if (threadIdx.x == 0) sh[0] = r;
    }
    __syncthreads();
    float res = sh[0];
    __syncthreads();
    return res;
}

// packed f32x2 FMA: d += a * b (elementwise on 2 packed floats)
__device__ __forceinline__ void ffma2(ull& d, ull a, ull b) {
    asm("fma.rn.f32x2 %0, %1, %2, %0;" : "+l"(d) : "l"(a), "l"(b));
}

// ---------------- K1: top-k / rank-selected indices -------------------------
__global__ void k_idx(const float* __restrict__ qr, const int* __restrict__ rnd) {
    int t = threadIdx.x;
    if (t < 16) {
        int b = t >> 2;
        const float* v = qr + t * FR;   // [B,Q,F], t=b*Q+q
        int hi = 0; float hv = v[0];
        for (int i = 1; i < FR; i++) { float x = v[i]; if (x > hv) { hv = x; hi = i; } }
        int r = rnd[t];
        int lo = 0;
        for (int i = 0; i < FR; i++) {
            int rank = 0;
            float c = v[i];
            for (int j = 0; j < FR; j++) {
                float a = v[j];
                rank += (a < c) || (a == c && j < i);
            }
            if (rank == r) { lo = i; break; }
        }
        g_high[t] = hi;
        g_low[t]  = lo;
        g_rowbf[t]      = b * FR + hi;   // compact rows 0..15 : high
        g_rowbf[16 + t] = b * FR + lo;   // compact rows 16..31: low
    }
}

// ---------------- K2: per-region inv norms + normalized maxpool of input ----
__global__ void __launch_bounds__(256) k_rmax(const float* __restrict__ inp) {
    int bf = blockIdx.x;             // b*20+f, 80 blocks
    int t  = threadIdx.x;
    __shared__ float sh[32];
    __shared__ float s_inv[OBJN];
    const float* base = inp + (size_t)bf * (OBJN * DD);

    for (int o = 0; o < OBJN; o++) {
        const float4* p = (const float4*)(base + o * DD);
        float s = 0.f;
        #pragma unroll
        for (int i = 0; i < 4; i++) {
            float4 v = __ldg(p + t + i * 256);
            s += v.x*v.x + v.y*v.y + v.z*v.z + v.w*v.w;
        }
        float tot = blockReduceSum256(s, sh);
        if (t == 0) s_inv[o] = 1.0f / fmaxf(sqrtf(tot), 1e-12f);
    }
    __syncthreads();
    if (t < OBJN) g_invn[bf * OBJN + t] = s_inv[t];

    float4 mx[4];
    #pragma unroll
    for (int i = 0; i < 4; i++) mx[i] = make_float4(-3.4e38f, -3.4e38f, -3.4e38f, -3.4e38f);
    for (int o = 0; o < OBJN; o++) {
        float inv = s_inv[o];
        const float4* p = (const float4*)(base + o * DD);
        #pragma unroll
        for (int i = 0; i < 4; i++) {
            float4 v = __ldg(p + t + i * 256);
            mx[i].x = fmaxf(mx[i].x, v.x * inv);
            mx[i].y = fmaxf(mx[i].y, v.y * inv);
            mx[i].z = fmaxf(mx[i].z, v.z * inv);
            mx[i].w = fmaxf(mx[i].w, v.w * inv);
        }
    }
    float s = 0.f;
    #pragma unroll
    for (int i = 0; i < 4; i++) s += mx[i].x*mx[i].x + mx[i].y*mx[i].y + mx[i].z*mx[i].z + mx[i].w*mx[i].w;
    float tot = blockReduceSum256(s, sh);
    float inv2 = 1.0f / fmaxf(sqrtf(tot), 1e-12f);
    float4* op = (float4*)(g_Rmax + (size_t)bf * DD);
    #pragma unroll
    for (int i = 0; i < 4; i++) {
        float4 v = mx[i];
        v.x *= inv2; v.y *= inv2; v.z *= inv2; v.w *= inv2;
        op[t + i * 256] = v;
    }
}

// ---------------- K3: mem maxpool + normalize (dominant, 655 MB stream) -----
__global__ void __launch_bounds__(256) k_memmp(const float* __restrict__ mem1,
                                               const float* __restrict__ mem2) {
    int m = blockIdx.x, sel = blockIdx.y;
    const float* mem = sel ? mem2 : mem1;
    int t = threadIdx.x;
    __shared__ float sh[32];
    const float4* base = (const float4*)(mem + (size_t)m * (OBJN * DD));
    float4 mx[4];
    #pragma unroll
    for (int i = 0; i < 4; i++) mx[i] = make_float4(-3.4e38f, -3.4e38f, -3.4e38f, -3.4e38f);
    for (int o = 0; o < OBJN; o++) {
        const float4* p = base + o * (DD / 4);
        #pragma unroll
        for (int i = 0; i < 4; i++) {
            float4 v = __ldcs(p + t + i * 256);   // streaming: don't pollute L2
            mx[i].x = fmaxf(mx[i].x, v.x);
            mx[i].y = fmaxf(mx[i].y, v.y);
            mx[i].z = fmaxf(mx[i].z, v.z);
            mx[i].w = fmaxf(mx[i].w, v.w);
        }
    }
    float s = 0.f;
    #pragma unroll
    for (int i = 0; i < 4; i++) s += mx[i].x*mx[i].x + mx[i].y*mx[i].y + mx[i].z*mx[i].z + mx[i].w*mx[i].w;
    float tot = blockReduceSum256(s, sh);
    float inv = 1.0f / fmaxf(sqrtf(tot), 1e-12f);
    float4* op = (float4*)(g_memmp + ((size_t)sel * MCNT + m) * DD);
    #pragma unroll
    for (int i = 0; i < 4; i++) {
        float4 v = mx[i];
        v.x *= inv; v.y *= inv; v.z *= inv; v.w *= inv;
        op[t + i * 256] = v;
    }
}

// ---------------- K4: fp32 score GEMM (32 x 1000 x 4096), f32x2, k-split ----
// Round-2 proven config: KSPLIT=16, 128-col m-tiles, 4x4 f32x2 accumulators.
__global__ void __launch_bounds__(256) k_scores() {
    int sel = blockIdx.z;
    int m0  = blockIdx.x * 128;             // 8 m-tiles of 128
    int kb  = blockIdx.y * (DD / KSPLIT);   // 256-wide K segment
    int t   = threadIdx.x;
    __shared__ float Rs[NROWS][64];         // [row][k]
    __shared__ float Ms[128][66];           // [col][k]  (pad 66: 8B-aligned)
    __shared__ int   rowbase[NROWS];
    if (t < NROWS) rowbase[t] = g_rowbf[t] * DD;

    ull acc[4][4];
    #pragma unroll
    for (int i = 0; i < 4; i++)
        #pragma unroll
        for (int j = 0; j < 4; j++) acc[i][j] = 0ull;

    const float* memmp = g_memmp + (size_t)sel * MCNT * DD;
    int c  = t & 31;     // base col
    int rt = t >> 5;     // row group 0..7 -> rows rt*4 .. rt*4+3

    for (int kc = 0; kc < DD / KSPLIT; kc += 64) {   // 4 chunks of 64
        __syncthreads();
        int k0 = kb + kc;
        for (int i = t; i < NROWS * 64; i += 256) {
            int r = i >> 6, k = i & 63;
            Rs[r][k] = g_Rmax[rowbase[r] + k0 + k];
        }
        for (int i = t; i < 128 * 16; i += 256) {
            int cc = i >> 4, kq = (i & 15) << 2;     // kq = 0,4,...,60
            int m = m0 + cc;
            float4 v = (m < MCNT)
                ? __ldg((const float4*)(memmp + (size_t)m * DD + k0 + kq))
                : make_float4(0.f, 0.f, 0.f, 0.f);
            ull* w = (ull*)&Ms[cc][kq];              // 8B-aligned
            ull w0, w1;
            asm("mov.b64 %0, {%1,%2};" : "=l"(w0) : "f"(v.x), "f"(v.y));
            asm("mov.b64 %0, {%1,%2};" : "=l"(w1) : "f"(v.z), "f"(v.w));
            w[0] = w0; w[1] = w1;
        }
        __syncthreads();
        #pragma unroll 8
        for (int k = 0; k < 64; k += 2) {
            ull rv[4], mv[4];
            #pragma unroll
            for (int i = 0; i < 4; i++) rv[i] = *(const ull*)&Rs[rt * 4 + i][k];
            #pragma unroll
            for (int j = 0; j < 4; j++) mv[j] = *(const ull*)&Ms[c + j * 32][k];
            #pragma unroll
            for (int i = 0; i < 4; i++)
                #pragma unroll
                for (int j = 0; j < 4; j++) ffma2(acc[i][j], rv[i], mv[j]);
        }
    }
    float* part = g_part + (((size_t)blockIdx.y * 2 + sel) * NROWS) * 1024;
    #pragma unroll
    for (int i = 0; i < 4; i++)
        #pragma unroll
        for (int j = 0; j < 4; j++) {
            unsigned lo, hi;
            asm("mov.b64 {%0,%1}, %2;" : "=r"(lo), "=r"(hi) : "l"(acc[i][j]));
            float s = __uint_as_float(lo) + __uint_as_float(hi);
            int row = rt * 4 + i;
            int m   = m0 + c + j * 32;
            part[row * 1024 + m] = s;
        }
}

// ---------------- K4b: deterministic reduce + argmax (+ sim outputs) --------
__global__ void __launch_bounds__(256) k_argmax(float* __restrict__ out) {
    int row = blockIdx.x;            // 0..63
    int sel = row >> 5, r = row & 31;
    int t = threadIdx.x;
    __shared__ unsigned long long sh[8];
    unsigned long long best = 0ull;
    for (int m = t; m < MCNT; m += 256) {
        float s = 0.f;
        #pragma unroll
        for (int ks = 0; ks < KSPLIT; ks++)
            s += g_part[(((size_t)ks * 2 + sel) * NROWS + r) * 1024 + m];
        unsigned u = __float_as_uint(s);
        u ^= (u >> 31) ? 0xFFFFFFFFu : 0x80000000u;
        unsigned long long pv = ((unsigned long long)u << 32) | (unsigned)(0xFFFFFFFFu - (unsigned)m);
        best = (pv > best) ? pv : best;
    }
    #pragma unroll
    for (int o = 16; o > 0; o >>= 1) {
        unsigned long long x = __shfl_xor_sync(0xffffffffu, best, o);
        best = (x > best) ? x : best;
    }
    if ((t & 31) == 0) sh[t >> 5] = best;
    __syncthreads();
    if (t == 0) {
        #pragma unroll
        for (int w = 1; w < 8; w++) best = (sh[w] > best) ? sh[w] : best;
        int sim = (int)(0xFFFFFFFFu - (unsigned)(best & 0xFFFFFFFFu));
        g_sim[sel * 32 + r] = sim;
        if (sel == 1 && r < 16) {
            int b = r >> 2, q = r & 3;
            out[OUT_HIGH + q * 4 + b] = (float)sim;   // sim2 at high row
        }
        if (sel == 0 && r >= 16) {
            int bq = r - 16;
            int b = bq >> 2, q = bq & 3;
            out[OUT_LOW + q * 4 + b] = (float)sim;    // sim1 at low row
        }
    }
}

// ---------------- K5a: plain output frames (no g_sim dependency) ------------
__global__ void __launch_bounds__(256) k_out_plain(const float* __restrict__ inp,
                                                   float* __restrict__ out) {
    int id = blockIdx.x;             // 0..319 == q*80 + b*20 + f
    int o  = blockIdx.y;             // 0..19
    int q  = id / 80;
    int rem = id - q * 80;
    int b  = rem / FR;
    int f  = rem - b * FR;
    int bq = b * QQ + q;
    if (f == g_high[bq] || f == g_low[bq]) return;   // handled by k_out_spec
    int t  = threadIdx.x;

    size_t outoff = ((size_t)id * OBJN + o) * DD;
    float4* op = (float4*)(out + outoff);                 // Rp
    float4* on = (float4*)(out + RP_ELEMS + outoff);      // Rn
    const float4* pr = (const float4*)(inp + (((size_t)(b * FR + f)) * OBJN + o) * DD);
    float invn = g_invn[(b * FR + f) * OBJN + o];

    #pragma unroll
    for (int i = 0; i < 4; i++) {
        float4 v = __ldg(pr + t + i * 256);
        v.x *= invn; v.y *= invn; v.z *= invn; v.w *= invn;
        __stcs(op + t + i * 256, v);
        __stcs(on + t + i * 256, v);
    }
}

// ---------------- K5b: hi/lo output frames (needs g_sim) --------------------
__global__ void __launch_bounds__(256) k_out_spec(const float* __restrict__ inp,
                                                  const float* __restrict__ mem1,
                                                  const float* __restrict__ mem2,
                                                  float* __restrict__ out) {
    int s  = blockIdx.x;             // 0..31: [kind][bq]
    int o  = blockIdx.y;             // 0..19
    int bq = s & 15;
    int kind = s >> 4;               // 0: f=hi, 1: f=lo
    int b = bq >> 2, q = bq & 3;
    int hi = g_high[bq], lo = g_low[bq];
    int f  = kind ? lo : hi;
    int id = q * 80 + b * FR + f;
    int t  = threadIdx.x;

    size_t outoff = ((size_t)id * OBJN + o) * DD;
    float4* op = (float4*)(out + outoff);                 // Rp
    float4* on = (float4*)(out + RP_ELEMS + outoff);      // Rn
    const float4* pr = (const float4*)(inp + (((size_t)(b * FR + f)) * OBJN + o) * DD);
    float invn = g_invn[(b * FR + f) * OBJN + o];

    if (kind == 0) {
        // f == hi: Rn <- mem2[sim2 @ low]; Rp <- R
        int sm = g_sim[32 + 16 + bq];
        const float4* pm = (const float4*)(mem2 + (size_t)sm * (OBJN * DD) + o * DD);
        #pragma unroll
        for (int i = 0; i < 4; i++) {
            float4 v = __ldg(pr + t + i * 256);
            v.x *= invn; v.y *= invn; v.z *= invn; v.w *= invn;
            __stcs(op + t + i * 256, v);
            float4 w = __ldg(pm + t + i * 256);
            __stcs(on + t + i * 256, w);
        }
    } else {
        // f == lo: Rp <- mem1[sim1 @ low]; Rn <- R
        int sm = g_sim[16 + bq];
        const float4* pm = (const float4*)(mem1 + (size_t)sm * (OBJN * DD) + o * DD);
        #pragma unroll
        for (int i = 0; i < 4; i++) {
            float4 w = __ldg(pm + t + i * 256);
            __stcs(op + t + i * 256, w);
            float4 v = __ldg(pr + t + i * 256);
            v.x *= invn; v.y *= invn; v.z *= invn; v.w *= invn;
            __stcs(on + t + i * 256, v);
        }
    }
}

// ---------------- launch -----------------------------------------------------
extern "C" void kernel_launch(void* const* d_in, const int* in_sizes, int n_in,
                              void* d_out, int out_size) {
    const float* qr   = (const float*)d_in[0];   // [4,4,20]
    const float* inp  = (const float*)d_in[1];   // [4,20,20,4096]
    const float* mem1 = (const float*)d_in[2];   // [1000,81920]
    const float* mem2 = (const float*)d_in[3];   // [1000,81920]
    const int*   rnd  = (const int*)d_in[4];     // [4,4,1]
    float* out = (float*)d_out;

    // one-time resources (no device memory involved)
    static cudaStream_t s2 = nullptr;
    static cudaEvent_t evA = nullptr, evB = nullptr;
    if (s2 == nullptr) {
        cudaStreamCreateWithFlags(&s2, cudaStreamNonBlocking);
        cudaEventCreateWithFlags(&evA, cudaEventDisableTiming);
        cudaEventCreateWithFlags(&evB, cudaEventDisableTiming);
    }

    // main stream: index + input normalization (producers for both branches)
    k_idx<<<1, 32>>>(qr, rnd);
    k_rmax<<<80, 256>>>(inp);
    cudaEventRecord(evA, 0);

    // side stream: bulk output writes (independent of memory-bank pipeline)
    cudaStreamWaitEvent(s2, evA, 0);
    k_out_plain<<<dim3(320, OBJN), 256, 0, s2>>>(inp, out);
    cudaEventRecord(evB, s2);

    // main stream: memory-bank pipeline (critical path)
    k_memmp<<<dim3(MCNT, 2), 256>>>(mem1, mem2);
    k_scores<<<dim3(8, KSPLIT, 2), 256>>>();
    k_argmax<<<64, 256>>>(out);
    k_out_spec<<<dim3(32, OBJN), 256>>>(inp, mem1, mem2, out);

    // join
    cudaStreamWaitEvent(0, evB, 0);
}

// round 7
// speedup vs baseline: 1.2850x; 1.0556x over previous
#include <cuda_runtime.h>
#include <cstdint>

// Problem constants
#define DD   4096
#define OBJN 20
#define MCNT 1000
#define FR   20
#define BB   4
#define QQ   4
#define NROWS 32      // compacted rows: 16 high + 16 low
#define MPB  4        // memory rows per block in fused kernel

#define RP_ELEMS 26214400ull          // Q*B*F*OBJ*D
#define OUT_HIGH (2ull*RP_ELEMS)      // 52428800
#define OUT_LOW  (2ull*RP_ELEMS + 16ull)

typedef unsigned long long ull;

// ---------------- scratch (device globals; no allocation allowed) ----------
__device__ int   g_high[16];
__device__ int   g_low[16];
__device__ int   g_rowbf[32];                 // compact row -> b*20+f
__device__ float g_invn[BB*FR*OBJN];          // per-region inverse norms
__device__ float g_Rmax[BB*FR*DD];            // normalized max-pooled input rows
__device__ float g_score[2*NROWS*1024];       // [sel][row][m] final scores
__device__ int   g_sim[64];                   // [sel][32] argmax results

// ---------------- helpers ---------------------------------------------------
__device__ __forceinline__ float blockReduceSum256(float v, float* sh) {
    #pragma unroll
    for (int o = 16; o > 0; o >>= 1) v += __shfl_xor_sync(0xffffffffu, v, o);
    int lane = threadIdx.x & 31, w = threadIdx.x >> 5;
    if (lane == 0) sh[w] = v;
    __syncthreads();
    if (threadIdx.x < 32) {
        float r = (threadIdx.x < 8) ? sh[threadIdx.x] : 0.f;
        #pragma unroll
        for (int o = 4; o > 0; o >>= 1) r += __shfl_xor_sync(0xffffffffu, r, o);
        if (threadIdx.x == 0) sh[0] = r;
    }
    __syncthreads();
    float res = sh[0];
    __syncthreads();
    return res;
}

// ---------------- K1: top-k / rank-selected indices -------------------------
__global__ void k_idx(const float* __restrict__ qr, const int* __restrict__ rnd) {
    int t = threadIdx.x;
    if (t < 16) {
        int b = t >> 2;
        const float* v = qr + t * FR;   // [B,Q,F], t=b*Q+q
        int hi = 0; float hv = v[0];
        for (int i = 1; i < FR; i++) { float x = v[i]; if (x > hv) { hv = x; hi = i; } }
        int r = rnd[t];
        int lo = 0;
        for (int i = 0; i < FR; i++) {
            int rank = 0;
            float c = v[i];
            for (int j = 0; j < FR; j++) {
                float a = v[j];
                rank += (a < c) || (a == c && j < i);
            }
            if (rank == r) { lo = i; break; }
        }
        g_high[t] = hi;
        g_low[t]  = lo;
        g_rowbf[t]      = b * FR + hi;   // compact rows 0..15 : high
        g_rowbf[16 + t] = b * FR + lo;   // compact rows 16..31: low
    }
}

// ---------------- K2: per-region inv norms + normalized maxpool of input ----
__global__ void __launch_bounds__(256) k_rmax(const float* __restrict__ inp) {
    int bf = blockIdx.x;             // b*20+f, 80 blocks
    int t  = threadIdx.x;
    __shared__ float sh[32];
    __shared__ float s_inv[OBJN];
    const float* base = inp + (size_t)bf * (OBJN * DD);

    for (int o = 0; o < OBJN; o++) {
        const float4* p = (const float4*)(base + o * DD);
        float s = 0.f;
        #pragma unroll
        for (int i = 0; i < 4; i++) {
            float4 v = __ldg(p + t + i * 256);
            s += v.x*v.x + v.y*v.y + v.z*v.z + v.w*v.w;
        }
        float tot = blockReduceSum256(s, sh);
        if (t == 0) s_inv[o] = 1.0f / fmaxf(sqrtf(tot), 1e-12f);
    }
    __syncthreads();
    if (t < OBJN) g_invn[bf * OBJN + t] = s_inv[t];

    float4 mx[4];
    #pragma unroll
    for (int i = 0; i < 4; i++) mx[i] = make_float4(-3.4e38f, -3.4e38f, -3.4e38f, -3.4e38f);
    for (int o = 0; o < OBJN; o++) {
        float inv = s_inv[o];
        const float4* p = (const float4*)(base + o * DD);
        #pragma unroll
        for (int i = 0; i < 4; i++) {
            float4 v = __ldg(p + t + i * 256);
            mx[i].x = fmaxf(mx[i].x, v.x * inv);
            mx[i].y = fmaxf(mx[i].y, v.y * inv);
            mx[i].z = fmaxf(mx[i].z, v.z * inv);
            mx[i].w = fmaxf(mx[i].w, v.w * inv);
        }
    }
    float s = 0.f;
    #pragma unroll
    for (int i = 0; i < 4; i++) s += mx[i].x*mx[i].x + mx[i].y*mx[i].y + mx[i].z*mx[i].z + mx[i].w*mx[i].w;
    float tot = blockReduceSum256(s, sh);
    float inv2 = 1.0f / fmaxf(sqrtf(tot), 1e-12f);
    float4* op = (float4*)(g_Rmax + (size_t)bf * DD);
    #pragma unroll
    for (int i = 0; i < 4; i++) {
        float4 v = mx[i];
        v.x *= inv2; v.y *= inv2; v.z *= inv2; v.w *= inv2;
        op[t + i * 256] = v;
    }
}

// ---------------- K3: FUSED mem maxpool + normalize + 32-row dot products ---
// Each block: one sel, MPB=4 consecutive memory rows. Streams 1.3 MB from
// DRAM (the dominant 655 MB total), keeps the 4 pooled rows in registers,
// then dots them against all 32 normalized Rmax rows (L2-hot, 512 KB
// amortized over 4 m-rows). Dot-product FMAs hide in the DRAM-wait issue
// slots (issue was 7.6% in the unfused kernel). Fully deterministic order.
__global__ void __launch_bounds__(256) k_fused(const float* __restrict__ mem1,
                                               const float* __restrict__ mem2) {
    int sel = blockIdx.y;
    int m0  = blockIdx.x * MPB;
    const float* mem = sel ? mem2 : mem1;
    int t = threadIdx.x, lane = t & 31, w = t >> 5;
    __shared__ float sh[32];
    __shared__ float s_inv[MPB];
    __shared__ int   rb[NROWS];              // Rmax row base (float4 units)
    __shared__ float s_red[NROWS][8][MPB];   // per-warp dot partials (4 KB)
    if (t < NROWS) rb[t] = g_rowbf[t] * (DD / 4);

    float4 pm[MPB][4];                       // pooled rows, 16 floats each
    #pragma unroll
    for (int mi = 0; mi < MPB; mi++) {
        #pragma unroll
        for (int i = 0; i < 4; i++)
            pm[mi][i] = make_float4(-3.4e38f, -3.4e38f, -3.4e38f, -3.4e38f);
        const float4* base = (const float4*)(mem + (size_t)(m0 + mi) * (OBJN * DD));
        for (int o = 0; o < OBJN; o++) {
            const float4* p = base + o * (DD / 4);
            #pragma unroll
            for (int i = 0; i < 4; i++) {
                float4 v = __ldcs(p + t + i * 256);   // streaming
                pm[mi][i].x = fmaxf(pm[mi][i].x, v.x);
                pm[mi][i].y = fmaxf(pm[mi][i].y, v.y);
                pm[mi][i].z = fmaxf(pm[mi][i].z, v.z);
                pm[mi][i].w = fmaxf(pm[mi][i].w, v.w);
            }
        }
        float s = 0.f;
        #pragma unroll
        for (int i = 0; i < 4; i++)
            s += pm[mi][i].x*pm[mi][i].x + pm[mi][i].y*pm[mi][i].y
               + pm[mi][i].z*pm[mi][i].z + pm[mi][i].w*pm[mi][i].w;
        float tot = blockReduceSum256(s, sh);    // has syncthreads (covers rb too)
        if (t == 0) s_inv[mi] = 1.0f / fmaxf(sqrtf(tot), 1e-12f);
    }

    // dot vs 32 Rmax rows; per-warp partials accumulated without syncs
    for (int r = 0; r < NROWS; r++) {
        const float4* R4 = ((const float4*)g_Rmax) + rb[r] + t;
        float p0 = 0.f, p1 = 0.f, p2 = 0.f, p3 = 0.f;
        #pragma unroll
        for (int i = 0; i < 4; i++) {
            float4 rv = __ldg(R4 + i * 256);
            p0 += pm[0][i].x*rv.x + pm[0][i].y*rv.y + pm[0][i].z*rv.z + pm[0][i].w*rv.w;
            p1 += pm[1][i].x*rv.x + pm[1][i].y*rv.y + pm[1][i].z*rv.z + pm[1][i].w*rv.w;
            p2 += pm[2][i].x*rv.x + pm[2][i].y*rv.y + pm[2][i].z*rv.z + pm[2][i].w*rv.w;
            p3 += pm[3][i].x*rv.x + pm[3][i].y*rv.y + pm[3][i].z*rv.z + pm[3][i].w*rv.w;
        }
        #pragma unroll
        for (int o = 16; o > 0; o >>= 1) {
            p0 += __shfl_xor_sync(0xffffffffu, p0, o);
            p1 += __shfl_xor_sync(0xffffffffu, p1, o);
            p2 += __shfl_xor_sync(0xffffffffu, p2, o);
            p3 += __shfl_xor_sync(0xffffffffu, p3, o);
        }
        if (lane == 0) {
            s_red[r][w][0] = p0; s_red[r][w][1] = p1;
            s_red[r][w][2] = p2; s_red[r][w][3] = p3;
        }
    }
    __syncthreads();
    if (t < NROWS * MPB) {               // 128 threads: one (row, mi) each
        int r = t >> 2, mi = t & 3;
        float s = 0.f;
        #pragma unroll
        for (int ww = 0; ww < 8; ww++) s += s_red[r][ww][mi];
        g_score[((size_t)sel * NROWS + r) * 1024 + m0 + mi] = s * s_inv[mi];
    }
}

// ---------------- K4: deterministic argmax over 1000 scores (+ sim outputs) -
__global__ void __launch_bounds__(256) k_argmax(float* __restrict__ out) {
    int row = blockIdx.x;            // 0..63 == sel*32 + r
    int sel = row >> 5, r = row & 31;
    int t = threadIdx.x;
    __shared__ unsigned long long sh[8];
    unsigned long long best = 0ull;
    const float* sc = g_score + (size_t)row * 1024;
    for (int m = t; m < MCNT; m += 256) {
        unsigned u = __float_as_uint(sc[m]);
        u ^= (u >> 31) ? 0xFFFFFFFFu : 0x80000000u;
        unsigned long long pv = ((unsigned long long)u << 32) | (unsigned)(0xFFFFFFFFu - (unsigned)m);
        best = (pv > best) ? pv : best;
    }
    #pragma unroll
    for (int o = 16; o > 0; o >>= 1) {
        unsigned long long x = __shfl_xor_sync(0xffffffffu, best, o);
        best = (x > best) ? x : best;
    }
    if ((t & 31) == 0) sh[t >> 5] = best;
    __syncthreads();
    if (t == 0) {
        #pragma unroll
        for (int w = 1; w < 8; w++) best = (sh[w] > best) ? sh[w] : best;
        int sim = (int)(0xFFFFFFFFu - (unsigned)(best & 0xFFFFFFFFu));
        g_sim[sel * 32 + r] = sim;
        if (sel == 1 && r < 16) {
            int b = r >> 2, q = r & 3;
            out[OUT_HIGH + q * 4 + b] = (float)sim;   // sim2 at high row
        }
        if (sel == 0 && r >= 16) {
            int bq = r - 16;
            int b = bq >> 2, q = bq & 3;
            out[OUT_LOW + q * 4 + b] = (float)sim;    // sim1 at low row
        }
    }
}

// ---------------- K5: assemble Rp / Rn (210 MB writes) ----------------------
__global__ void __launch_bounds__(256) k_out(const float* __restrict__ inp,
                                             const float* __restrict__ mem1,
                                             const float* __restrict__ mem2,
                                             float* __restrict__ out) {
    int id = blockIdx.x;             // 0..319 == q*80 + b*20 + f
    int o  = blockIdx.y;             // 0..19
    int q  = id / 80;
    int rem = id - q * 80;
    int b  = rem / FR;
    int f  = rem - b * FR;
    int bq = b * QQ + q;
    int hi = g_high[bq], lo = g_low[bq];
    int t  = threadIdx.x;

    size_t outoff = ((size_t)id * OBJN + o) * DD;
    float4* op = (float4*)(out + outoff);                 // Rp
    float4* on = (float4*)(out + RP_ELEMS + outoff);      // Rn
    const float4* pr = (const float4*)(inp + (((size_t)(b * FR + f)) * OBJN + o) * DD);
    float invn = g_invn[(b * FR + f) * OBJN + o];

    if (f != hi && f != lo) {
        #pragma unroll
        for (int i = 0; i < 4; i++) {
            float4 v = __ldg(pr + t + i * 256);
            v.x *= invn; v.y *= invn; v.z *= invn; v.w *= invn;
            __stcs(op + t + i * 256, v);
            __stcs(on + t + i * 256, v);
        }
    } else if (f == hi) {
        // Rn <- mem2[sim2 @ low]; Rp <- R
        int s = g_sim[32 + 16 + bq];
        const float4* pm = (const float4*)(mem2 + (size_t)s * (OBJN * DD) + o * DD);
        #pragma unroll
        for (int i = 0; i < 4; i++) {
            float4 v = __ldg(pr + t + i * 256);
            v.x *= invn; v.y *= invn; v.z *= invn; v.w *= invn;
            __stcs(op + t + i * 256, v);
            float4 w = __ldg(pm + t + i * 256);
            __stcs(on + t + i * 256, w);
        }
    } else {
        // f == lo: Rp <- mem1[sim1 @ low]; Rn <- R
        int s = g_sim[16 + bq];
        const float4* pm = (const float4*)(mem1 + (size_t)s * (OBJN * DD) + o * DD);
        #pragma unroll
        for (int i = 0; i < 4; i++) {
            float4 w = __ldg(pm + t + i * 256);
            __stcs(op + t + i * 256, w);
            float4 v = __ldg(pr + t + i * 256);
            v.x *= invn; v.y *= invn; v.z *= invn; v.w *= invn;
            __stcs(on + t + i * 256, v);
        }
    }
}

// ---------------- launch -----------------------------------------------------
extern "C" void kernel_launch(void* const* d_in, const int* in_sizes, int n_in,
                              void* d_out, int out_size) {
    const float* qr   = (const float*)d_in[0];   // [4,4,20]
    const float* inp  = (const float*)d_in[1];   // [4,20,20,4096]
    const float* mem1 = (const float*)d_in[2];   // [1000,81920]
    const float* mem2 = (const float*)d_in[3];   // [1000,81920]
    const int*   rnd  = (const int*)d_in[4];     // [4,4,1]
    float* out = (float*)d_out;

    k_idx<<<1, 32>>>(qr, rnd);
    k_rmax<<<80, 256>>>(inp);
    k_fused<<<dim3(MCNT / MPB, 2), 256>>>(mem1, mem2);
    k_argmax<<<64, 256>>>(out);
    k_out<<<dim3(320, OBJN), 256>>>(inp, mem1, mem2, out);
}

// round 8
// speedup vs baseline: 1.3329x; 1.0373x over previous
#include <cuda_runtime.h>
#include <cstdint>

// Problem constants
#define DD   4096
#define OBJN 20
#define MCNT 1000
#define FR   20
#define BB   4
#define QQ   4
#define NROWS 32      // compacted rows: 16 high + 16 low
#define MPB  4        // memory rows per block in fused kernel

#define RP_ELEMS 26214400ull          // Q*B*F*OBJ*D
#define OUT_HIGH (2ull*RP_ELEMS)      // 52428800
#define OUT_LOW  (2ull*RP_ELEMS + 16ull)

typedef unsigned long long ull;

// ---------------- scratch (device globals; no allocation allowed) ----------
__device__ int   g_high[16];
__device__ int   g_low[16];
__device__ int   g_rowbf[32];                 // compact row -> b*20+f
__device__ float g_invn[BB*FR*OBJN];          // per-region inverse norms
__device__ float g_Rmax[BB*FR*DD];            // normalized max-pooled input rows
__device__ float g_score[2*NROWS*1024];       // [sel][row][m] final scores
__device__ int   g_sim[64];                   // [sel][32] argmax results

// ---------------- helpers ---------------------------------------------------
__device__ __forceinline__ float blockReduceSum256(float v, float* sh) {
    #pragma unroll
    for (int o = 16; o > 0; o >>= 1) v += __shfl_xor_sync(0xffffffffu, v, o);
    int lane = threadIdx.x & 31, w = threadIdx.x >> 5;
    if (lane == 0) sh[w] = v;
    __syncthreads();
    if (threadIdx.x < 32) {
        float r = (threadIdx.x < 8) ? sh[threadIdx.x] : 0.f;
        #pragma unroll
        for (int o = 4; o > 0; o >>= 1) r += __shfl_xor_sync(0xffffffffu, r, o);
        if (threadIdx.x == 0) sh[0] = r;
    }
    __syncthreads();
    float res = sh[0];
    __syncthreads();
    return res;
}

__device__ __forceinline__ void ffma2(ull& d, ull a, ull b) {
    asm("fma.rn.f32x2 %0, %1, %2, %0;" : "+l"(d) : "l"(a), "l"(b));
}
__device__ __forceinline__ ull packf2(float x, float y) {
    ull r; asm("mov.b64 %0, {%1,%2};" : "=l"(r) : "f"(x), "f"(y)); return r;
}
__device__ __forceinline__ float unpack_add(ull a) {
    unsigned lo, hi;
    asm("mov.b64 {%0,%1}, %2;" : "=r"(lo), "=r"(hi) : "l"(a));
    return __uint_as_float(lo) + __uint_as_float(hi);
}

// ---------------- K2: idx (block 0) + per-region norms + normalized maxpool -
__global__ void __launch_bounds__(256) k_rmax(const float* __restrict__ qr,
                                              const int* __restrict__ rnd,
                                              const float* __restrict__ inp) {
    int bf = blockIdx.x;             // b*20+f, 80 blocks
    int t  = threadIdx.x;

    // block 0 side-work: top-k / rank-selected indices (no block sync needed:
    // consumers are later kernels)
    if (bf == 0 && t < 16) {
        int b = t >> 2;
        const float* v = qr + t * FR;   // [B,Q,F], t=b*Q+q
        int hi = 0; float hv = v[0];
        for (int i = 1; i < FR; i++) { float x = v[i]; if (x > hv) { hv = x; hi = i; } }
        int r = rnd[t];
        int lo = 0;
        for (int i = 0; i < FR; i++) {
            int rank = 0;
            float c = v[i];
            for (int j = 0; j < FR; j++) {
                float a = v[j];
                rank += (a < c) || (a == c && j < i);
            }
            if (rank == r) { lo = i; break; }
        }
        g_high[t] = hi;
        g_low[t]  = lo;
        g_rowbf[t]      = b * FR + hi;
        g_rowbf[16 + t] = b * FR + lo;
    }

    __shared__ float sh[32];
    __shared__ float s_inv[OBJN];
    const float* base = inp + (size_t)bf * (OBJN * DD);

    for (int o = 0; o < OBJN; o++) {
        const float4* p = (const float4*)(base + o * DD);
        float s = 0.f;
        #pragma unroll
        for (int i = 0; i < 4; i++) {
            float4 v = __ldg(p + t + i * 256);
            s += v.x*v.x + v.y*v.y + v.z*v.z + v.w*v.w;
        }
        float tot = blockReduceSum256(s, sh);
        if (t == 0) s_inv[o] = 1.0f / fmaxf(sqrtf(tot), 1e-12f);
    }
    __syncthreads();
    if (t < OBJN) g_invn[bf * OBJN + t] = s_inv[t];

    float4 mx[4];
    #pragma unroll
    for (int i = 0; i < 4; i++) mx[i] = make_float4(-3.4e38f, -3.4e38f, -3.4e38f, -3.4e38f);
    for (int o = 0; o < OBJN; o++) {
        float inv = s_inv[o];
        const float4* p = (const float4*)(base + o * DD);
        #pragma unroll
        for (int i = 0; i < 4; i++) {
            float4 v = __ldg(p + t + i * 256);
            mx[i].x = fmaxf(mx[i].x, v.x * inv);
            mx[i].y = fmaxf(mx[i].y, v.y * inv);
            mx[i].z = fmaxf(mx[i].z, v.z * inv);
            mx[i].w = fmaxf(mx[i].w, v.w * inv);
        }
    }
    float s = 0.f;
    #pragma unroll
    for (int i = 0; i < 4; i++) s += mx[i].x*mx[i].x + mx[i].y*mx[i].y + mx[i].z*mx[i].z + mx[i].w*mx[i].w;
    float tot = blockReduceSum256(s, sh);
    float inv2 = 1.0f / fmaxf(sqrtf(tot), 1e-12f);
    float4* op = (float4*)(g_Rmax + (size_t)bf * DD);
    #pragma unroll
    for (int i = 0; i < 4; i++) {
        float4 v = mx[i];
        v.x *= inv2; v.y *= inv2; v.z *= inv2; v.w *= inv2;
        op[t + i * 256] = v;
    }
}

// ---------------- K3: FUSED mem maxpool + normalize + 32-row dots (f32x2) ---
__global__ void __launch_bounds__(256) k_fused(const float* __restrict__ mem1,
                                               const float* __restrict__ mem2) {
    int sel = blockIdx.y;
    int m0  = blockIdx.x * MPB;
    const float* mem = sel ? mem2 : mem1;
    int t = threadIdx.x, lane = t & 31, w = t >> 5;
    __shared__ float sh[32];
    __shared__ float s_inv[MPB];
    __shared__ int   rb[NROWS];              // Rmax row base (float4 units)
    __shared__ float s_red[NROWS][8][MPB];   // per-warp dot partials (4 KB)
    if (t < NROWS) rb[t] = g_rowbf[t] * (DD / 4);

    float4 pm[MPB][4];                       // pooled rows, 16 floats each
    #pragma unroll
    for (int mi = 0; mi < MPB; mi++) {
        #pragma unroll
        for (int i = 0; i < 4; i++)
            pm[mi][i] = make_float4(-3.4e38f, -3.4e38f, -3.4e38f, -3.4e38f);
        const float4* base = (const float4*)(mem + (size_t)(m0 + mi) * (OBJN * DD));
        for (int o = 0; o < OBJN; o++) {
            const float4* p = base + o * (DD / 4);
            #pragma unroll
            for (int i = 0; i < 4; i++) {
                float4 v = __ldcs(p + t + i * 256);   // streaming
                pm[mi][i].x = fmaxf(pm[mi][i].x, v.x);
                pm[mi][i].y = fmaxf(pm[mi][i].y, v.y);
                pm[mi][i].z = fmaxf(pm[mi][i].z, v.z);
                pm[mi][i].w = fmaxf(pm[mi][i].w, v.w);
            }
        }
        float s = 0.f;
        #pragma unroll
        for (int i = 0; i < 4; i++)
            s += pm[mi][i].x*pm[mi][i].x + pm[mi][i].y*pm[mi][i].y
               + pm[mi][i].z*pm[mi][i].z + pm[mi][i].w*pm[mi][i].w;
        float tot = blockReduceSum256(s, sh);    // has syncthreads (covers rb)
        if (t == 0) s_inv[mi] = 1.0f / fmaxf(sqrtf(tot), 1e-12f);
    }

    // pack pooled rows to f32x2
    ull pp[MPB][8];
    #pragma unroll
    for (int mi = 0; mi < MPB; mi++)
        #pragma unroll
        for (int i = 0; i < 4; i++) {
            pp[mi][2*i]   = packf2(pm[mi][i].x, pm[mi][i].y);
            pp[mi][2*i+1] = packf2(pm[mi][i].z, pm[mi][i].w);
        }

    // dot vs 32 Rmax rows with packed FFMA2 (half the issue slots)
    for (int r = 0; r < NROWS; r++) {
        const float4* R4 = ((const float4*)g_Rmax) + rb[r] + t;
        ull a0 = 0ull, a1 = 0ull, a2 = 0ull, a3 = 0ull;
        #pragma unroll
        for (int i = 0; i < 4; i++) {
            float4 rv = __ldg(R4 + i * 256);
            ull r0 = packf2(rv.x, rv.y), r1 = packf2(rv.z, rv.w);
            ffma2(a0, pp[0][2*i], r0); ffma2(a0, pp[0][2*i+1], r1);
            ffma2(a1, pp[1][2*i], r0); ffma2(a1, pp[1][2*i+1], r1);
            ffma2(a2, pp[2][2*i], r0); ffma2(a2, pp[2][2*i+1], r1);
            ffma2(a3, pp[3][2*i], r0); ffma2(a3, pp[3][2*i+1], r1);
        }
        float p0 = unpack_add(a0), p1 = unpack_add(a1);
        float p2 = unpack_add(a2), p3 = unpack_add(a3);
        #pragma unroll
        for (int o = 16; o > 0; o >>= 1) {
            p0 += __shfl_xor_sync(0xffffffffu, p0, o);
            p1 += __shfl_xor_sync(0xffffffffu, p1, o);
            p2 += __shfl_xor_sync(0xffffffffu, p2, o);
            p3 += __shfl_xor_sync(0xffffffffu, p3, o);
        }
        if (lane == 0) {
            s_red[r][w][0] = p0; s_red[r][w][1] = p1;
            s_red[r][w][2] = p2; s_red[r][w][3] = p3;
        }
    }
    __syncthreads();
    if (t < NROWS * MPB) {               // 128 threads: one (row, mi) each
        int r = t >> 2, mi = t & 3;
        float s = 0.f;
        #pragma unroll
        for (int ww = 0; ww < 8; ww++) s += s_red[r][ww][mi];
        g_score[((size_t)sel * NROWS + r) * 1024 + m0 + mi] = s * s_inv[mi];
    }
}

// ---------------- K4: deterministic argmax over 1000 scores (+ sim outputs) -
__global__ void __launch_bounds__(256) k_argmax(float* __restrict__ out) {
    int row = blockIdx.x;            // 0..63 == sel*32 + r
    int sel = row >> 5, r = row & 31;
    int t = threadIdx.x;
    __shared__ unsigned long long sh[8];
    unsigned long long best = 0ull;
    const float* sc = g_score + (size_t)row * 1024;
    for (int m = t; m < MCNT; m += 256) {
        unsigned u = __float_as_uint(sc[m]);
        u ^= (u >> 31) ? 0xFFFFFFFFu : 0x80000000u;
        unsigned long long pv = ((unsigned long long)u << 32) | (unsigned)(0xFFFFFFFFu - (unsigned)m);
        best = (pv > best) ? pv : best;
    }
    #pragma unroll
    for (int o = 16; o > 0; o >>= 1) {
        unsigned long long x = __shfl_xor_sync(0xffffffffu, best, o);
        best = (x > best) ? x : best;
    }
    if ((t & 31) == 0) sh[t >> 5] = best;
    __syncthreads();
    if (t == 0) {
        #pragma unroll
        for (int w = 1; w < 8; w++) best = (sh[w] > best) ? sh[w] : best;
        int sim = (int)(0xFFFFFFFFu - (unsigned)(best & 0xFFFFFFFFu));
        g_sim[sel * 32 + r] = sim;
        if (sel == 1 && r < 16) {
            int b = r >> 2, q = r & 3;
            out[OUT_HIGH + q * 4 + b] = (float)sim;   // sim2 at high row
        }
        if (sel == 0 && r >= 16) {
            int bq = r - 16;
            int b = bq >> 2, q = bq & 3;
            out[OUT_LOW + q * 4 + b] = (float)sim;    // sim1 at low row
        }
    }
}

// ---------------- K5a: plain output frames (no g_sim dependency) ------------
__global__ void __launch_bounds__(256) k_out_plain(const float* __restrict__ inp,
                                                   float* __restrict__ out) {
    int id = blockIdx.x;             // 0..319 == q*80 + b*20 + f
    int o  = blockIdx.y;             // 0..19
    int q  = id / 80;
    int rem = id - q * 80;
    int b  = rem / FR;
    int f  = rem - b * FR;
    int bq = b * QQ + q;
    if (f == g_high[bq] || f == g_low[bq]) return;   // handled by k_out_spec
    int t  = threadIdx.x;

    size_t outoff = ((size_t)id * OBJN + o) * DD;
    float4* op = (float4*)(out + outoff);                 // Rp
    float4* on = (float4*)(out + RP_ELEMS + outoff);      // Rn
    const float4* pr = (const float4*)(inp + (((size_t)(b * FR + f)) * OBJN + o) * DD);
    float invn = g_invn[(b * FR + f) * OBJN + o];

    #pragma unroll
    for (int i = 0; i < 4; i++) {
        float4 v = __ldg(pr + t + i * 256);
        v.x *= invn; v.y *= invn; v.z *= invn; v.w *= invn;
        __stcs(op + t + i * 256, v);
        __stcs(on + t + i * 256, v);
    }
}

// ---------------- K5b: hi/lo output frames (needs g_sim) --------------------
__global__ void __launch_bounds__(256) k_out_spec(const float* __restrict__ inp,
                                                  const float* __restrict__ mem1,
                                                  const float* __restrict__ mem2,
                                                  float* __restrict__ out) {
    int s  = blockIdx.x;             // 0..31: [kind][bq]
    int o  = blockIdx.y;             // 0..19
    int bq = s & 15;
    int kind = s >> 4;               // 0: f=hi, 1: f=lo
    int b = bq >> 2, q = bq & 3;
    int hi = g_high[bq], lo = g_low[bq];
    int f  = kind ? lo : hi;
    int id = q * 80 + b * FR + f;
    int t  = threadIdx.x;

    size_t outoff = ((size_t)id * OBJN + o) * DD;
    float4* op = (float4*)(out + outoff);                 // Rp
    float4* on = (float4*)(out + RP_ELEMS + outoff);      // Rn
    const float4* pr = (const float4*)(inp + (((size_t)(b * FR + f)) * OBJN + o) * DD);
    float invn = g_invn[(b * FR + f) * OBJN + o];

    if (kind == 0) {
        // f == hi: Rn <- mem2[sim2 @ low]; Rp <- R
        int sm = g_sim[32 + 16 + bq];
        const float4* pm = (const float4*)(mem2 + (size_t)sm * (OBJN * DD) + o * DD);
        #pragma unroll
        for (int i = 0; i < 4; i++) {
            float4 v = __ldg(pr + t + i * 256);
            v.x *= invn; v.y *= invn; v.z *= invn; v.w *= invn;
            __stcs(op + t + i * 256, v);
            float4 w = __ldg(pm + t + i * 256);
            __stcs(on + t + i * 256, w);
        }
    } else {
        // f == lo: Rp <- mem1[sim1 @ low]; Rn <- R
        int sm = g_sim[16 + bq];
        const float4* pm = (const float4*)(mem1 + (size_t)sm * (OBJN * DD) + o * DD);
        #pragma unroll
        for (int i = 0; i < 4; i++) {
            float4 w = __ldg(pm + t + i * 256);
            __stcs(op + t + i * 256, w);
            float4 v = __ldg(pr + t + i * 256);
            v.x *= invn; v.y *= invn; v.z *= invn; v.w *= invn;
            __stcs(on + t + i * 256, v);
        }
    }
}

// ---------------- launch -----------------------------------------------------
extern "C" void kernel_launch(void* const* d_in, const int* in_sizes, int n_in,
                              void* d_out, int out_size) {
    const float* qr   = (const float*)d_in[0];   // [4,4,20]
    const float* inp  = (const float*)d_in[1];   // [4,20,20,4096]
    const float* mem1 = (const float*)d_in[2];   // [1000,81920]
    const float* mem2 = (const float*)d_in[3];   // [1000,81920]
    const int*   rnd  = (const int*)d_in[4];     // [4,4,1]
    float* out = (float*)d_out;

    static cudaStream_t s2 = nullptr;
    static cudaEvent_t evA = nullptr, evB = nullptr;
    if (s2 == nullptr) {
        cudaStreamCreateWithFlags(&s2, cudaStreamNonBlocking);
        cudaEventCreateWithFlags(&evA, cudaEventDisableTiming);
        cudaEventCreateWithFlags(&evB, cudaEventDisableTiming);
    }

    // main: idx (in rmax blk0) + input normalization
    k_rmax<<<80, 256>>>(qr, rnd, inp);
    cudaEventRecord(evA, 0);

    // side stream: bulk output writes overlap the fused mem stream
    cudaStreamWaitEvent(s2, evA, 0);
    k_out_plain<<<dim3(320, OBJN), 256, 0, s2>>>(inp, out);
    cudaEventRecord(evB, s2);

    // main: fused pooling+scores, argmax, special frames
    k_fused<<<dim3(MCNT / MPB, 2), 256>>>(mem1, mem2);
    k_argmax<<<64, 256>>>(out);
    k_out_spec<<<dim3(32, OBJN), 256>>>(inp, mem1, mem2, out);

    // join
    cudaStreamWaitEvent(0, evB, 0);
}

// round 11
// speedup vs baseline: 1.3685x; 1.0267x over previous
#include <cuda_runtime.h>
#include <cstdint>

// Problem constants
#define DD   4096
#define OBJN 20
#define MCNT 1000
#define FR   20
#define BB   4
#define QQ   4
#define NROWS 32      // compacted rows: 16 high + 16 low
#define MPB  4        // memory rows per fused block
#define NFUSED 500    // (MCNT/MPB)*2
#define NPLAIN 6400   // 320 frame-slots * 20 obj
#define ILV  14       // interleave: every ILV-th block is fused

#define RP_ELEMS 26214400ull          // Q*B*F*OBJ*D
#define OUT_HIGH (2ull*RP_ELEMS)      // 52428800
#define OUT_LOW  (2ull*RP_ELEMS + 16ull)

typedef unsigned long long ull;

// ---------------- scratch (device globals; no allocation allowed) ----------
__device__ int   g_high[16];
__device__ int   g_low[16];
__device__ int   g_rowbf[32];                 // compact row -> b*20+f
__device__ float g_invn[BB*FR*OBJN];          // per-region inverse norms
__device__ float g_Rmax[BB*FR*DD];            // normalized max-pooled input rows
__device__ float g_score[2*NROWS*1024];       // [sel][row][m] final scores
__device__ int   g_sim[64];                   // [sel][32] argmax results

// ---------------- helpers ---------------------------------------------------
__device__ __forceinline__ float blockReduceSum256(float v, float* sh) {
    #pragma unroll
    for (int o = 16; o > 0; o >>= 1) v += __shfl_xor_sync(0xffffffffu, v, o);
    int lane = threadIdx.x & 31, w = threadIdx.x >> 5;
    if (lane == 0) sh[w] = v;
    __syncthreads();
    if (threadIdx.x < 32) {
        float r = (threadIdx.x < 8) ? sh[threadIdx.x] : 0.f;
        #pragma unroll
        for (int o = 4; o > 0; o >>= 1) r += __shfl_xor_sync(0xffffffffu, r, o);
        if (threadIdx.x == 0) sh[0] = r;
    }
    __syncthreads();
    float res = sh[0];
    __syncthreads();
    return res;
}

__device__ __forceinline__ void ffma2(ull& d, ull a, ull b) {
    asm("fma.rn.f32x2 %0, %1, %2, %0;" : "+l"(d) : "l"(a), "l"(b));
}
__device__ __forceinline__ ull packf2(float x, float y) {
    ull r; asm("mov.b64 %0, {%1,%2};" : "=l"(r) : "f"(x), "f"(y)); return r;
}
__device__ __forceinline__ float unpack_add(ull a) {
    unsigned lo, hi;
    asm("mov.b64 {%0,%1}, %2;" : "=r"(lo), "=r"(hi) : "l"(a));
    return __uint_as_float(lo) + __uint_as_float(hi);
}

// ---------------- K1: idx (block 0) + per-region norms + normalized maxpool -
__global__ void __launch_bounds__(256) k_rmax(const float* __restrict__ qr,
                                              const int* __restrict__ rnd,
                                              const float* __restrict__ inp) {
    int bf = blockIdx.x;             // b*20+f, 80 blocks
    int t  = threadIdx.x;

    if (bf == 0 && t < 16) {
        int b = t >> 2;
        const float* v = qr + t * FR;   // [B,Q,F], t=b*Q+q
        int hi = 0; float hv = v[0];
        for (int i = 1; i < FR; i++) { float x = v[i]; if (x > hv) { hv = x; hi = i; } }
        int r = rnd[t];
        int lo = 0;
        for (int i = 0; i < FR; i++) {
            int rank = 0;
            float c = v[i];
            for (int j = 0; j < FR; j++) {
                float a = v[j];
                rank += (a < c) || (a == c && j < i);
            }
            if (rank == r) { lo = i; break; }
        }
        g_high[t] = hi;
        g_low[t]  = lo;
        g_rowbf[t]      = b * FR + hi;
        g_rowbf[16 + t] = b * FR + lo;
    }

    __shared__ float sh[32];
    __shared__ float s_inv[OBJN];
    const float* base = inp + (size_t)bf * (OBJN * DD);

    for (int o = 0; o < OBJN; o++) {
        const float4* p = (const float4*)(base + o * DD);
        float s = 0.f;
        #pragma unroll
        for (int i = 0; i < 4; i++) {
            float4 v = __ldg(p + t + i * 256);
            s += v.x*v.x + v.y*v.y + v.z*v.z + v.w*v.w;
        }
        float tot = blockReduceSum256(s, sh);
        if (t == 0) s_inv[o] = 1.0f / fmaxf(sqrtf(tot), 1e-12f);
    }
    __syncthreads();
    if (t < OBJN) g_invn[bf * OBJN + t] = s_inv[t];

    float4 mx[4];
    #pragma unroll
    for (int i = 0; i < 4; i++) mx[i] = make_float4(-3.4e38f, -3.4e38f, -3.4e38f, -3.4e38f);
    for (int o = 0; o < OBJN; o++) {
        float inv = s_inv[o];
        const float4* p = (const float4*)(base + o * DD);
        #pragma unroll
        for (int i = 0; i < 4; i++) {
            float4 v = __ldg(p + t + i * 256);
            mx[i].x = fmaxf(mx[i].x, v.x * inv);
            mx[i].y = fmaxf(mx[i].y, v.y * inv);
            mx[i].z = fmaxf(mx[i].z, v.z * inv);
            mx[i].w = fmaxf(mx[i].w, v.w * inv);
        }
    }
    float s = 0.f;
    #pragma unroll
    for (int i = 0; i < 4; i++) s += mx[i].x*mx[i].x + mx[i].y*mx[i].y + mx[i].z*mx[i].z + mx[i].w*mx[i].w;
    float tot = blockReduceSum256(s, sh);
    float inv2 = 1.0f / fmaxf(sqrtf(tot), 1e-12f);
    float4* op = (float4*)(g_Rmax + (size_t)bf * DD);
    #pragma unroll
    for (int i = 0; i < 4; i++) {
        float4 v = mx[i];
        v.x *= inv2; v.y *= inv2; v.z *= inv2; v.w *= inv2;
        op[t + i * 256] = v;
    }
}

// ---------------- K2: MIXED kernel — fused mem pipeline + plain output copy -
// Every ILV-th block streams MPB memory rows (pool+norm+dots); the rest copy
// plain output tiles. Long-lived fused blocks accumulate residency (~200 of
// ~444) keeping the 655MB read stream saturated while copy blocks fill the
// write bandwidth — true read/write mixing without streams.
__global__ void __launch_bounds__(256) k_main(const float* __restrict__ mem1,
                                              const float* __restrict__ mem2,
                                              const float* __restrict__ inp,
                                              float* __restrict__ out) {
    int bx = blockIdx.x;
    int t  = threadIdx.x;

    __shared__ float sh[32];
    __shared__ float s_inv[MPB];
    __shared__ int   rb[NROWS];
    __shared__ float s_red[NROWS][8][MPB];

    if (bx % ILV == 0) {
        // ----- fused memory-bank work -----
        int f_id = bx / ILV;                 // 0..499
        int sel  = f_id & 1;
        int m0   = (f_id >> 1) * MPB;
        const float* mem = sel ? mem2 : mem1;
        int lane = t & 31, w = t >> 5;
        int rstart = sel ? 0 : 16;           // sel0 only needs low rows
        if (t < NROWS) rb[t] = g_rowbf[t] * (DD / 4);

        float4 pm[MPB][4];
        #pragma unroll
        for (int mi = 0; mi < MPB; mi++) {
            #pragma unroll
            for (int i = 0; i < 4; i++)
                pm[mi][i] = make_float4(-3.4e38f, -3.4e38f, -3.4e38f, -3.4e38f);
            const float4* base = (const float4*)(mem + (size_t)(m0 + mi) * (OBJN * DD));
            for (int o = 0; o < OBJN; o++) {
                const float4* p = base + o * (DD / 4);
                #pragma unroll
                for (int i = 0; i < 4; i++) {
                    float4 v = __ldcs(p + t + i * 256);
                    pm[mi][i].x = fmaxf(pm[mi][i].x, v.x);
                    pm[mi][i].y = fmaxf(pm[mi][i].y, v.y);
                    pm[mi][i].z = fmaxf(pm[mi][i].z, v.z);
                    pm[mi][i].w = fmaxf(pm[mi][i].w, v.w);
                }
            }
            float s = 0.f;
            #pragma unroll
            for (int i = 0; i < 4; i++)
                s += pm[mi][i].x*pm[mi][i].x + pm[mi][i].y*pm[mi][i].y
                   + pm[mi][i].z*pm[mi][i].z + pm[mi][i].w*pm[mi][i].w;
            float tot = blockReduceSum256(s, sh);    // syncthreads covers rb
            if (t == 0) s_inv[mi] = 1.0f / fmaxf(sqrtf(tot), 1e-12f);
        }

        ull pp[MPB][8];
        #pragma unroll
        for (int mi = 0; mi < MPB; mi++)
            #pragma unroll
            for (int i = 0; i < 4; i++) {
                pp[mi][2*i]   = packf2(pm[mi][i].x, pm[mi][i].y);
                pp[mi][2*i+1] = packf2(pm[mi][i].z, pm[mi][i].w);
            }

        for (int r = rstart; r < NROWS; r++) {
            const float4* R4 = ((const float4*)g_Rmax) + rb[r] + t;
            ull a0 = 0ull, a1 = 0ull, a2 = 0ull, a3 = 0ull;
            #pragma unroll
            for (int i = 0; i < 4; i++) {
                float4 rv = __ldg(R4 + i * 256);
                ull r0 = packf2(rv.x, rv.y), r1 = packf2(rv.z, rv.w);
                ffma2(a0, pp[0][2*i], r0); ffma2(a0, pp[0][2*i+1], r1);
                ffma2(a1, pp[1][2*i], r0); ffma2(a1, pp[1][2*i+1], r1);
                ffma2(a2, pp[2][2*i], r0); ffma2(a2, pp[2][2*i+1], r1);
                ffma2(a3, pp[3][2*i], r0); ffma2(a3, pp[3][2*i+1], r1);
            }
            float p0 = unpack_add(a0), p1 = unpack_add(a1);
            float p2 = unpack_add(a2), p3 = unpack_add(a3);
            #pragma unroll
            for (int o = 16; o > 0; o >>= 1) {
                p0 += __shfl_xor_sync(0xffffffffu, p0, o);
                p1 += __shfl_xor_sync(0xffffffffu, p1, o);
                p2 += __shfl_xor_sync(0xffffffffu, p2, o);
                p3 += __shfl_xor_sync(0xffffffffu, p3, o);
            }
            if (lane == 0) {
                s_red[r][w][0] = p0; s_red[r][w][1] = p1;
                s_red[r][w][2] = p2; s_red[r][w][3] = p3;
            }
        }
        __syncthreads();
        if (t < (NROWS * MPB)) {
            int r = t >> 2, mi = t & 3;
            if (r >= rstart) {
                float s = 0.f;
                #pragma unroll
                for (int ww = 0; ww < 8; ww++) s += s_red[r][ww][mi];
                g_score[((size_t)sel * NROWS + r) * 1024 + m0 + mi] = s * s_inv[mi];
            }
        }
    } else {
        // ----- plain output copy tile -----
        int p_id = bx - bx / ILV - 1;
        if (p_id >= NPLAIN) return;
        int id = p_id / OBJN;            // 0..319 == q*80 + b*20 + f
        int o  = p_id - id * OBJN;
        int q  = id / 80;
        int rem = id - q * 80;
        int b  = rem / FR;
        int f  = rem - b * FR;
        int bq = b * QQ + q;
        if (f == g_high[bq] || f == g_low[bq]) return;   // k_out_spec handles

        size_t outoff = ((size_t)id * OBJN + o) * DD;
        float4* op = (float4*)(out + outoff);                 // Rp
        float4* on = (float4*)(out + RP_ELEMS + outoff);      // Rn
        const float4* pr = (const float4*)(inp + (((size_t)(b * FR + f)) * OBJN + o) * DD);
        float invn = g_invn[(b * FR + f) * OBJN + o];

        #pragma unroll
        for (int i = 0; i < 4; i++) {
            float4 v = __ldg(pr + t + i * 256);
            v.x *= invn; v.y *= invn; v.z *= invn; v.w *= invn;
            __stcs(op + t + i * 256, v);
            __stcs(on + t + i * 256, v);
        }
    }
}

// ---------------- K3: deterministic argmax (+ sim outputs) ------------------
__global__ void __launch_bounds__(256) k_argmax(float* __restrict__ out) {
    int row = blockIdx.x;            // 0..63 == sel*32 + r
    int sel = row >> 5, r = row & 31;
    if (sel == 0 && r < 16) return;  // unused (sel0 high rows not computed)
    int t = threadIdx.x;
    __shared__ unsigned long long sh[8];
    unsigned long long best = 0ull;
    const float* sc = g_score + (size_t)row * 1024;
    for (int m = t; m < MCNT; m += 256) {
        unsigned u = __float_as_uint(sc[m]);
        u ^= (u >> 31) ? 0xFFFFFFFFu : 0x80000000u;
        unsigned long long pv = ((unsigned long long)u << 32) | (unsigned)(0xFFFFFFFFu - (unsigned)m);
        best = (pv > best) ? pv : best;
    }
    #pragma unroll
    for (int o = 16; o > 0; o >>= 1) {
        unsigned long long x = __shfl_xor_sync(0xffffffffu, best, o);
        best = (x > best) ? x : best;
    }
    if ((t & 31) == 0) sh[t >> 5] = best;
    __syncthreads();
    if (t == 0) {
        #pragma unroll
        for (int w = 1; w < 8; w++) best = (sh[w] > best) ? sh[w] : best;
        int sim = (int)(0xFFFFFFFFu - (unsigned)(best & 0xFFFFFFFFu));
        g_sim[sel * 32 + r] = sim;
        if (sel == 1 && r < 16) {
            int b = r >> 2, q = r & 3;
            out[OUT_HIGH + q * 4 + b] = (float)sim;   // sim2 at high row
        }
        if (sel == 0 && r >= 16) {
            int bq = r - 16;
            int b = bq >> 2, q = bq & 3;
            out[OUT_LOW + q * 4 + b] = (float)sim;    // sim1 at low row
        }
    }
}

// ---------------- K4: hi/lo output frames (needs g_sim) ---------------------
__global__ void __launch_bounds__(256) k_out_spec(const float* __restrict__ inp,
                                                  const float* __restrict__ mem1,
                                                  const float* __restrict__ mem2,
                                                  float* __restrict__ out) {
    int s  = blockIdx.x;             // 0..31: [kind][bq]
    int o  = blockIdx.y;             // 0..19
    int bq = s & 15;
    int kind = s >> 4;               // 0: f=hi, 1: f=lo
    int b = bq >> 2, q = bq & 3;
    int hi = g_high[bq], lo = g_low[bq];
    int f  = kind ? lo : hi;
    int id = q * 80 + b * FR + f;
    int t  = threadIdx.x;

    size_t outoff = ((size_t)id * OBJN + o) * DD;
    float4* op = (float4*)(out + outoff);                 // Rp
    float4* on = (float4*)(out + RP_ELEMS + outoff);      // Rn
    const float4* pr = (const float4*)(inp + (((size_t)(b * FR + f)) * OBJN + o) * DD);
    float invn = g_invn[(b * FR + f) * OBJN + o];

    if (kind == 0) {
        // f == hi: Rn <- mem2[sim2 @ low]; Rp <- R
        int sm = g_sim[32 + 16 + bq];
        const float4* pm = (const float4*)(mem2 + (size_t)sm * (OBJN * DD) + o * DD);
        #pragma unroll
        for (int i = 0; i < 4; i++) {
            float4 v = __ldg(pr + t + i * 256);
            v.x *= invn; v.y *= invn; v.z *= invn; v.w *= invn;
            __stcs(op + t + i * 256, v);
            float4 w = __ldg(pm + t + i * 256);
            __stcs(on + t + i * 256, w);
        }
    } else {
        // f == lo: Rp <- mem1[sim1 @ low]; Rn <- R
        int sm = g_sim[16 + bq];
        const float4* pm = (const float4*)(mem1 + (size_t)sm * (OBJN * DD) + o * DD);
        #pragma unroll
        for (int i = 0; i < 4; i++) {
            float4 w = __ldg(pm + t + i * 256);
            __stcs(op + t + i * 256, w);
            float4 v = __ldg(pr + t + i * 256);
            v.x *= invn; v.y *= invn; v.z *= invn; v.w *= invn;
            __stcs(on + t + i * 256, v);
        }
    }
}

// ---------------- launch -----------------------------------------------------
extern "C" void kernel_launch(void* const* d_in, const int* in_sizes, int n_in,
                              void* d_out, int out_size) {
    const float* qr   = (const float*)d_in[0];   // [4,4,20]
    const float* inp  = (const float*)d_in[1];   // [4,20,20,4096]
    const float* mem1 = (const float*)d_in[2];   // [1000,81920]
    const float* mem2 = (const float*)d_in[3];   // [1000,81920]
    const int*   rnd  = (const int*)d_in[4];     // [4,4,1]
    float* out = (float*)d_out;

    k_rmax<<<80, 256>>>(qr, rnd, inp);
    k_main<<<7000, 256>>>(mem1, mem2, inp, out);
    k_argmax<<<64, 256>>>(out);
    k_out_spec<<<dim3(32, OBJN), 256>>>(inp, mem1, mem2, out);
}